// round 7
// baseline (speedup 1.0000x reference)
#include <cuda_runtime.h>
#include <cuda_fp16.h>
#include <math.h>
#include <stdint.h>

#define Bsz 4
#define Nn 2048
#define Ee 128
#define Kk 3072            // C*P
#define Mm 16384           // 2*B*N rows (sig half then mem half)
#define HALF_WIN 15
#define NCHUNK 48          // 3072 / 64

// ---------------- scratch ----------------
__device__ float g_embed[Mm * Ee];           // pre-BN y = conv(x)+bias
__device__ float g_psum[2 * 16 * Ee];
__device__ float g_psumsq[2 * 16 * Ee];
__device__ float g_attn_band[Bsz * Nn * 32];
__device__ uint4 g_w0u[49152];               // W main bf16  [128 rows][384 uint4]
__device__ uint4 g_w1u[49152];               // W residual bf16

// ---------------- helpers ----------------
__device__ __forceinline__ uint32_t smem_u32(const void* p) {
    uint32_t a;
    asm("{ .reg .u64 t; cvta.to.shared.u64 t, %1; cvt.u32.u64 %0, t; }" : "=r"(a) : "l"(p));
    return a;
}
__device__ __forceinline__ void ldsm4(uint32_t addr, uint32_t* r) {
    asm volatile("ldmatrix.sync.aligned.m8n8.x4.shared.b16 {%0,%1,%2,%3}, [%4];"
                 : "=r"(r[0]), "=r"(r[1]), "=r"(r[2]), "=r"(r[3]) : "r"(addr));
}
__device__ __forceinline__ void ldsm2t(uint32_t addr, uint32_t* r) {
    asm volatile("ldmatrix.sync.aligned.m8n8.x2.trans.shared.b16 {%0,%1}, [%2];"
                 : "=r"(r[0]), "=r"(r[1]) : "r"(addr));
}
__device__ __forceinline__ void mma16816(float* c, const uint32_t* a, const uint32_t* b) {
    asm volatile(
        "mma.sync.aligned.m16n8k16.row.col.f32.bf16.bf16.f32 "
        "{%0,%1,%2,%3}, {%4,%5,%6,%7}, {%8,%9}, {%0,%1,%2,%3};"
        : "+f"(c[0]), "+f"(c[1]), "+f"(c[2]), "+f"(c[3])
        : "r"(a[0]), "r"(a[1]), "r"(a[2]), "r"(a[3]), "r"(b[0]), "r"(b[1]));
}
__device__ __forceinline__ void mma16816h(float* c, const uint32_t* a, const uint32_t* b) {
    asm volatile(
        "mma.sync.aligned.m16n8k16.row.col.f32.f16.f16.f32 "
        "{%0,%1,%2,%3}, {%4,%5,%6,%7}, {%8,%9}, {%0,%1,%2,%3};"
        : "+f"(c[0]), "+f"(c[1]), "+f"(c[2]), "+f"(c[3])
        : "r"(a[0]), "r"(a[1]), "r"(a[2]), "r"(a[3]), "r"(b[0]), "r"(b[1]));
}
#define CP_ASYNC16(dst, src) \
    asm volatile("cp.async.ca.shared.global [%0], [%1], 16;" :: "r"(dst), "l"(src) : "memory")
#define CP_COMMIT  asm volatile("cp.async.commit_group;" ::: "memory")
#define CP_WAIT0   asm volatile("cp.async.wait_group 0;" ::: "memory")

// ---------------- K_nop: filler so ncu's fixed launch index hits k_gemm ----
__global__ void k_nop() {}

// ---------------- K0: pre-split W into bf16 main + residual ----------------
__global__ void k_wsplit(const float* __restrict__ w) {
    int t = blockIdx.x * blockDim.x + threadIdx.x;   // 49152 threads, 8 floats each
    int i0 = t * 8;
    float4 u = *(const float4*)&w[i0];
    float4 v = *(const float4*)&w[i0 + 4];
    uint32_t p0, p1, p2, p3, r0, r1, r2, r3;
    asm("cvt.rn.bf16x2.f32 %0, %1, %2;" : "=r"(p0) : "f"(u.y), "f"(u.x));
    asm("cvt.rn.bf16x2.f32 %0, %1, %2;" : "=r"(p1) : "f"(u.w), "f"(u.z));
    asm("cvt.rn.bf16x2.f32 %0, %1, %2;" : "=r"(p2) : "f"(v.y), "f"(v.x));
    asm("cvt.rn.bf16x2.f32 %0, %1, %2;" : "=r"(p3) : "f"(v.w), "f"(v.z));
    float e0 = u.x - __uint_as_float(p0 << 16);
    float e1 = u.y - __uint_as_float(p0 & 0xffff0000u);
    float e2 = u.z - __uint_as_float(p1 << 16);
    float e3 = u.w - __uint_as_float(p1 & 0xffff0000u);
    float e4 = v.x - __uint_as_float(p2 << 16);
    float e5 = v.y - __uint_as_float(p2 & 0xffff0000u);
    float e6 = v.z - __uint_as_float(p3 << 16);
    float e7 = v.w - __uint_as_float(p3 & 0xffff0000u);
    asm("cvt.rn.bf16x2.f32 %0, %1, %2;" : "=r"(r0) : "f"(e1), "f"(e0));
    asm("cvt.rn.bf16x2.f32 %0, %1, %2;" : "=r"(r1) : "f"(e3), "f"(e2));
    asm("cvt.rn.bf16x2.f32 %0, %1, %2;" : "=r"(r2) : "f"(e5), "f"(e4));
    asm("cvt.rn.bf16x2.f32 %0, %1, %2;" : "=r"(r3) : "f"(e7), "f"(e6));
    g_w0u[t] = make_uint4(p0, p1, p2, p3);
    g_w1u[t] = make_uint4(r0, r1, r2, r3);
}

// ---------------- K1: HMMA embed GEMM (bf16 3-term split) ----------------
// CTA: M=64 x N=128; 8 warps, warp tile 32x32; K chunks of 64.
// smem per stage: A0 8KB, A1 8KB, B0 16KB, B1 16KB = 48KB; 2 stages = 96KB.
#define ST_A0 0
#define ST_A1 8192
#define ST_B0 16384
#define ST_B1 32768
#define ST_SZ 49152
#define GEMM_SMEM (1024 + 2 * ST_SZ)

__device__ __forceinline__ void conv_store2(const float4* pv, char* base0, char* base1,
                                            const uint32_t* offs) {
#pragma unroll
    for (int q = 0; q < 2; q++) {
        float4 u = pv[2 * q];
        float4 v = pv[2 * q + 1];
        uint32_t p0, p1, p2, p3, r0, r1, r2, r3;
        asm("cvt.rn.bf16x2.f32 %0, %1, %2;" : "=r"(p0) : "f"(u.y), "f"(u.x));
        asm("cvt.rn.bf16x2.f32 %0, %1, %2;" : "=r"(p1) : "f"(u.w), "f"(u.z));
        asm("cvt.rn.bf16x2.f32 %0, %1, %2;" : "=r"(p2) : "f"(v.y), "f"(v.x));
        asm("cvt.rn.bf16x2.f32 %0, %1, %2;" : "=r"(p3) : "f"(v.w), "f"(v.z));
        float e0 = u.x - __uint_as_float(p0 << 16);
        float e1 = u.y - __uint_as_float(p0 & 0xffff0000u);
        float e2 = u.z - __uint_as_float(p1 << 16);
        float e3 = u.w - __uint_as_float(p1 & 0xffff0000u);
        float e4 = v.x - __uint_as_float(p2 << 16);
        float e5 = v.y - __uint_as_float(p2 & 0xffff0000u);
        float e6 = v.z - __uint_as_float(p3 << 16);
        float e7 = v.w - __uint_as_float(p3 & 0xffff0000u);
        asm("cvt.rn.bf16x2.f32 %0, %1, %2;" : "=r"(r0) : "f"(e1), "f"(e0));
        asm("cvt.rn.bf16x2.f32 %0, %1, %2;" : "=r"(r1) : "f"(e3), "f"(e2));
        asm("cvt.rn.bf16x2.f32 %0, %1, %2;" : "=r"(r2) : "f"(e5), "f"(e4));
        asm("cvt.rn.bf16x2.f32 %0, %1, %2;" : "=r"(r3) : "f"(e7), "f"(e6));
        *(uint4*)(base0 + offs[q]) = make_uint4(p0, p1, p2, p3);
        *(uint4*)(base1 + offs[q]) = make_uint4(r0, r1, r2, r3);
    }
}

__global__ void __launch_bounds__(256, 2)
k_gemm(const float* __restrict__ sig, const float* __restrict__ mem,
       const float* __restrict__ bias) {
    extern __shared__ char smraw[];
    uint32_t sb = smem_u32(smraw);
    uint32_t ab = (sb + 1023) & ~1023u;
    char* sm = smraw + (ab - sb);

    int tid = threadIdx.x;
    int wid = tid >> 5, lane = tid & 31;

    int bm = blockIdx.x * 64;
    const float* X = (bm < 8192) ? sig : mem;
    int rb = (bm < 8192) ? bm : bm - 8192;

    // A staging: thread -> (row 0..63, quarter 0..3 of 16 floats)
    int rowA = tid >> 2;
    int ha = tid & 3;
    const float* arow = X + (size_t)(rb + rowA) * Kk + ha * 16;
    uint32_t offsA[2];
#pragma unroll
    for (int q = 0; q < 2; q++) {
        uint32_t o = (uint32_t)rowA * 128 + (uint32_t)ha * 32 + q * 16;
        offsA[q] = o ^ ((o >> 3) & 0x70);
    }

    // W cp.async: thread -> (e-row 0..127, half 0..1 of 64B)
    int rowW = tid >> 1;
    int hw = tid & 1;
    const uint4* w0p = g_w0u + rowW * 384 + hw * 4;
    const uint4* w1p = g_w1u + rowW * 384 + hw * 4;
    uint32_t offsW[4];
#pragma unroll
    for (int q = 0; q < 4; q++) {
        uint32_t o = (uint32_t)rowW * 128 + (uint32_t)hw * 64 + q * 16;
        offsW[q] = o ^ ((o >> 3) & 0x70);
    }

    // warp tile: 2 warps in M (32 rows) x 4 warps in N (32 cols)
    int mwrow = (wid >> 2) * 32;
    int nwcol = (wid & 3) * 32;

    float acc[2][4][4];
#pragma unroll
    for (int a = 0; a < 2; a++)
#pragma unroll
        for (int b = 0; b < 4; b++)
#pragma unroll
            for (int c = 0; c < 4; c++) acc[a][b][c] = 0.f;

    auto issueW = [&](int c, int s) {
        uint32_t b0 = ab + s * ST_SZ + ST_B0;
        uint32_t b1 = ab + s * ST_SZ + ST_B1;
        const uint4* s0 = w0p + c * 8;
        const uint4* s1 = w1p + c * 8;
#pragma unroll
        for (int q = 0; q < 4; q++) {
            CP_ASYNC16(b0 + offsW[q], s0 + q);
            CP_ASYNC16(b1 + offsW[q], s1 + q);
        }
        CP_COMMIT;
    };

    // prologue: chunk 0
    {
        issueW(0, 0);
        float4 pa[4];
#pragma unroll
        for (int q = 0; q < 4; q++) pa[q] = *(const float4*)(arow + q * 4);
        conv_store2(pa, sm + ST_A0, sm + ST_A1, offsA);
        CP_WAIT0;
    }
    __syncthreads();

    for (int c = 0; c < NCHUNK; c++) {
        int s = c & 1;
        bool more = (c + 1 < NCHUNK);
        float4 pa[4];
        if (more) {
            issueW(c + 1, s ^ 1);
            const float* ap = arow + (c + 1) * 64;
#pragma unroll
            for (int q = 0; q < 4; q++) pa[q] = *(const float4*)(ap + q * 4);
        }

        uint32_t A0 = ab + s * ST_SZ + ST_A0;
        uint32_t A1 = ab + s * ST_SZ + ST_A1;
        uint32_t B0 = ab + s * ST_SZ + ST_B0;
        uint32_t B1 = ab + s * ST_SZ + ST_B1;

#pragma unroll
        for (int j = 0; j < 4; j++) {
            uint32_t fa0[2][4], fa1[2][4];
#pragma unroll
            for (int mi = 0; mi < 2; mi++) {
                uint32_t row = mwrow + mi * 16 + (lane & 15);
                uint32_t off = row * 128 + ((lane >> 4) * 16) + j * 32;
                off ^= (off >> 3) & 0x70;
                ldsm4(A0 + off, fa0[mi]);
                ldsm4(A1 + off, fa1[mi]);
            }
#pragma unroll
            for (int p = 0; p < 2; p++) {
                uint32_t rowb = nwcol + p * 16 + (lane & 7) + ((lane >> 4) << 3);
                uint32_t off = rowb * 128 + (((lane >> 3) & 1) * 16) + j * 32;
                off ^= (off >> 3) & 0x70;
                uint32_t fb0[4], fb1[4];
                ldsm4(B0 + off, fb0);
                ldsm4(B1 + off, fb1);
                // per-p term-major: 4 independent accs between same-acc MMAs
#pragma unroll
                for (int mi = 0; mi < 2; mi++)
#pragma unroll
                    for (int hh = 0; hh < 2; hh++)
                        mma16816(acc[mi][2 * p + hh], fa0[mi], &fb0[2 * hh]);
#pragma unroll
                for (int mi = 0; mi < 2; mi++)
#pragma unroll
                    for (int hh = 0; hh < 2; hh++)
                        mma16816(acc[mi][2 * p + hh], fa1[mi], &fb0[2 * hh]);
#pragma unroll
                for (int mi = 0; mi < 2; mi++)
#pragma unroll
                    for (int hh = 0; hh < 2; hh++)
                        mma16816(acc[mi][2 * p + hh], fa0[mi], &fb1[2 * hh]);
            }
        }

        if (more) conv_store2(pa, sm + (s ^ 1) * ST_SZ + ST_A0, sm + (s ^ 1) * ST_SZ + ST_A1, offsA);
        CP_WAIT0;
        __syncthreads();
    }

    int g = lane >> 2, t4 = lane & 3;
#pragma unroll
    for (int mi = 0; mi < 2; mi++) {
        int row0 = bm + mwrow + mi * 16 + g;
#pragma unroll
        for (int tn = 0; tn < 4; tn++) {
            int col = nwcol + tn * 8 + 2 * t4;
            float bx = __ldg(&bias[col]);
            float by = __ldg(&bias[col + 1]);
            float2 o0 = make_float2(acc[mi][tn][0] + bx, acc[mi][tn][1] + by);
            float2 o1 = make_float2(acc[mi][tn][2] + bx, acc[mi][tn][3] + by);
            *(float2*)&g_embed[(size_t)row0 * Ee + col] = o0;
            *(float2*)&g_embed[(size_t)(row0 + 8) * Ee + col] = o1;
        }
    }
}

// ---------------- K2: BN partial sums (deterministic) ----------------
__global__ void k_bn_stats() {
    int e = threadIdx.x;
    int chunk = blockIdx.x;      // 0..15
    int half = blockIdx.y;
    int row0 = half * 8192 + chunk * 512;
    float s = 0.f, sq = 0.f;
#pragma unroll 4
    for (int r = 0; r < 512; r++) {
        float v = g_embed[(size_t)(row0 + r) * Ee + e];
        s += v;
        sq += v * v;
    }
    g_psum[(half * 16 + chunk) * Ee + e] = s;
    g_psumsq[(half * 16 + chunk) * Ee + e] = sq;
}

// ---------------- K4: banded sim + softmax (BN finalize + apply folded) ----
__global__ void k_attn(const float* __restrict__ gamma, const float* __restrict__ beta,
                       float* __restrict__ out_attn) {
    __shared__ float s_et[38 * 129];
    __shared__ float s_ex[8 * 128];
    __shared__ float s_band[8][32];
    __shared__ float s_sc[256], s_sh[256];
    int i0 = blockIdx.x * 8;
    int b = blockIdx.y;
    int jmin = max(0, i0 - HALF_WIN);
    int jmax = min(Nn - 1, i0 + 7 + HALF_WIN);
    int nj = jmax - jmin + 1;
    int tid = threadIdx.x;

    {
        int half = tid >> 7;
        int e = tid & 127;
        float s = 0.f, sq = 0.f;
#pragma unroll
        for (int c = 0; c < 16; c++) {
            s += g_psum[(half * 16 + c) * Ee + e];
            sq += g_psumsq[(half * 16 + c) * Ee + e];
        }
        float mean = s / 8192.f;
        float var = sq / 8192.f - mean * mean;
        float rstd = rsqrtf(var + 1e-5f);
        float sc = rstd * __ldg(&gamma[e]);
        s_sc[tid] = sc;
        s_sh[tid] = __ldg(&beta[e]) - mean * sc;
    }
    __syncthreads();

    for (int p = tid; p < nj * 128; p += 256) {
        int jr = p >> 7, k = p & 127;
        float v = g_embed[(size_t)(8192 + b * Nn + jmin + jr) * Ee + k] * s_sc[128 + k] + s_sh[128 + k];
        s_et[jr * 129 + k] = (v >= 0.f) ? v : 0.1f * v;
    }
    for (int p = tid; p < 8 * 128; p += 256) {
        int r = p >> 7, k = p & 127;
        float v = g_embed[(size_t)(b * Nn + i0 + r) * Ee + k] * s_sc[k] + s_sh[k];
        s_ex[r * 128 + k] = (v >= 0.f) ? v : 0.1f * v;
    }
    __syncthreads();

    int w = tid >> 5, lane = tid & 31;
    int i = i0 + w;
    int j0 = max(0, i - HALF_WIN);
    int j1 = min(Nn - 1, i + HALF_WIN);
    int width = j1 - j0 + 1;

    float sim = -1e30f;
    if (lane < width) {
        int jr = j0 + lane - jmin;
        float acc = 0.f;
        const float* ex = &s_ex[w * 128];
        const float* et = &s_et[jr * 129];
#pragma unroll 8
        for (int k = 0; k < 128; k++) acc += ex[k] * et[k];
        sim = acc;
    }
    float mx = sim;
#pragma unroll
    for (int o = 16; o; o >>= 1) mx = fmaxf(mx, __shfl_xor_sync(0xffffffffu, mx, o));
    float ev = (lane < width) ? expf(sim - mx) : 0.f;
    float sum = ev;
#pragma unroll
    for (int o = 16; o; o >>= 1) sum += __shfl_xor_sync(0xffffffffu, sum, o);
    float a = ev / sum;
    s_band[w][lane] = (lane < width) ? a : 0.f;
    if (lane < width) g_attn_band[(b * Nn + i) * 32 + lane] = a;
    __syncwarp();

    float* rowp = out_attn + ((size_t)(b * Nn + i)) * Nn;
#pragma unroll
    for (int t = 0; t < 16; t++) {
        int j4 = (t * 32 + lane) * 4;
        float4 o = make_float4(0.f, 0.f, 0.f, 0.f);
        if (j4 + 3 >= j0 && j4 <= j1) {
#pragma unroll
            for (int q = 0; q < 4; q++) {
                int j = j4 + q;
                if (j >= j0 && j <= j1) ((float*)&o)[q] = s_band[w][j - j0];
            }
        }
        *(float4*)&rowp[j4] = o;
    }
}

// ---------------- K5: banded attn @ mem via fp16 HMMA + blend --------------
__global__ void __launch_bounds__(256)
k_memw(const float* __restrict__ sig, const float* __restrict__ mem,
       float* __restrict__ out_mem) {
    __shared__ __half s_a0[16][56];
    __shared__ __half s_a1[16][56];
    __shared__ __half s_m[48][264];
    __shared__ float s_out[16][256];
    int i0 = blockIdx.x * 16;
    int fc = blockIdx.y * 256;
    int b = blockIdx.z;
    int tid = threadIdx.x;
    int jmin = max(0, i0 - HALF_WIN);
    int jmax = min(Nn - 1, i0 + 15 + HALF_WIN);
    int nj = jmax - jmin + 1; // <= 46

    for (int p = tid; p < 16 * 28; p += 256) {
        ((uint32_t*)s_a0)[p] = 0u;
        ((uint32_t*)s_a1)[p] = 0u;
    }
    __syncthreads();
    for (int q = tid; q < 16 * 32; q += 256) {
        int r = q >> 5, l = q & 31;
        int i = i0 + r;
        int j0 = max(0, i - HALF_WIN);
        int j1 = min(Nn - 1, i + HALF_WIN);
        if (l <= j1 - j0) {
            float a = g_attn_band[(b * Nn + i) * 32 + l];
            __half a0 = __float2half_rn(a);
            float res = a - __half2float(a0);
            s_a0[r][j0 - jmin + l] = a0;
            s_a1[r][j0 - jmin + l] = __float2half_rn(res);
        }
    }
    for (int p = tid; p < 48 * 64; p += 256) {
        int row = p >> 6, f4 = (p & 63) * 4;
        __half2 h0, h1;
        if (row < nj) {
            float4 v = *(const float4*)&mem[(size_t)(b * Nn + jmin + row) * Kk + fc + f4];
            h0 = __floats2half2_rn(v.x, v.y);
            h1 = __floats2half2_rn(v.z, v.w);
        } else {
            h0 = __floats2half2_rn(0.f, 0.f);
            h1 = h0;
        }
        *(__half2*)&s_m[row][f4] = h0;
        *(__half2*)&s_m[row][f4 + 2] = h1;
    }
    __syncthreads();

    int wid = tid >> 5, lane = tid & 31;
    uint32_t a0base = smem_u32(&s_a0[0][0]);
    uint32_t a1base = smem_u32(&s_a1[0][0]);
    uint32_t mbase = smem_u32(&s_m[0][0]);

    float acc[4][4];
#pragma unroll
    for (int t = 0; t < 4; t++)
#pragma unroll
        for (int c = 0; c < 4; c++) acc[t][c] = 0.f;

#pragma unroll
    for (int ks = 0; ks < 3; ks++) {
        uint32_t fa0[4], fa1[4];
        {
            uint32_t row = lane & 15;
            uint32_t coloff = ks * 16 + (lane >> 4) * 8;
            ldsm4(a0base + (row * 56 + coloff) * 2, fa0);
            ldsm4(a1base + (row * 56 + coloff) * 2, fa1);
        }
#pragma unroll
        for (int t = 0; t < 4; t++) {
            uint32_t ncol = (wid * 4 + t) * 8;
            uint32_t krow = ks * 16 + (lane & 15);
            uint32_t fb[2];
            ldsm2t(mbase + (krow * 264 + ncol) * 2, fb);
            mma16816h(acc[t], fa0, fb);
            mma16816h(acc[t], fa1, fb);
        }
    }

    int g = lane >> 2, c2 = (lane & 3) * 2;
#pragma unroll
    for (int t = 0; t < 4; t++) {
        int cb = wid * 32 + t * 8 + c2;
        s_out[g][cb] = acc[t][0];
        s_out[g][cb + 1] = acc[t][1];
        s_out[g + 8][cb] = acc[t][2];
        s_out[g + 8][cb + 1] = acc[t][3];
    }
    __syncthreads();

    for (int p = tid; p < 16 * 64; p += 256) {
        int r = p >> 6, f4 = (p & 63) * 4;
        size_t base = (size_t)(b * Nn + i0 + r) * Kk + fc + f4;
        float4 sg = *(const float4*)&sig[base];
        float4 mv = *(float4*)&s_out[r][f4];
        float4 o;
        o.x = 0.5f * sg.x + 0.5f * mv.x;
        o.y = 0.5f * sg.y + 0.5f * mv.y;
        o.z = 0.5f * sg.z + 0.5f * mv.z;
        o.w = 0.5f * sg.w + 0.5f * mv.w;
        *(float4*)&out_mem[base] = o;
    }
}

// ---------------- launch ----------------
extern "C" void kernel_launch(void* const* d_in, const int* in_sizes, int n_in,
                              void* d_out, int out_size) {
    const float* sig   = (const float*)d_in[0];
    const float* mem   = (const float*)d_in[1];
    const float* w     = (const float*)d_in[2];
    const float* bias  = (const float*)d_in[3];
    const float* gamma = (const float*)d_in[4];
    const float* beta  = (const float*)d_in[5];
    float* out_mem  = (float*)d_out;
    float* out_attn = (float*)d_out + (size_t)Bsz * Nn * Kk;

    static bool attr_done = false;
    if (!attr_done) {
        cudaFuncSetAttribute(k_gemm, cudaFuncAttributeMaxDynamicSharedMemorySize, GEMM_SMEM);
        attr_done = true;
    }

    k_wsplit<<<192, 256>>>(w);       // launch 0
    k_nop<<<1, 32>>>();              // launch 1 (filler)
    k_nop<<<1, 32>>>();              // launch 2 (filler)
    k_gemm<<<Mm / 64, 256, GEMM_SMEM>>>(sig, mem, bias);   // launch 3 -> ncu target
    k_bn_stats<<<dim3(16, 2), 128>>>();
    k_attn<<<dim3(Nn / 8, Bsz), 256>>>(gamma, beta, out_attn);
    k_memw<<<dim3(Nn / 16, 12, Bsz), 256>>>(sig, mem, out_mem);
}

// round 8
// speedup vs baseline: 1.4147x; 1.4147x over previous
#include <cuda_runtime.h>
#include <cuda_fp16.h>
#include <math.h>
#include <stdint.h>

#define Bsz 4
#define Nn 2048
#define Ee 128
#define Kk 3072            // C*P
#define Mm 16384           // 2*B*N rows (sig half then mem half)
#define HALF_WIN 15
#define NCHUNK 48          // 3072 / 64

// ---------------- scratch ----------------
__device__ float g_embed[Mm * Ee];           // pre-BN y = conv(x)+bias
__device__ float g_psum[2 * 32 * Ee];
__device__ float g_psumsq[2 * 32 * Ee];
__device__ float g_attn_band[Bsz * Nn * 32];
__device__ uint4 g_w0u[49152];               // W main bf16, CHUNK-major [48][128 rows][8 uint4]
__device__ uint4 g_w1u[49152];               // W residual bf16, same layout

// ---------------- helpers ----------------
__device__ __forceinline__ uint32_t smem_u32(const void* p) {
    uint32_t a;
    asm("{ .reg .u64 t; cvta.to.shared.u64 t, %1; cvt.u32.u64 %0, t; }" : "=r"(a) : "l"(p));
    return a;
}
__device__ __forceinline__ void ldsm4(uint32_t addr, uint32_t* r) {
    asm volatile("ldmatrix.sync.aligned.m8n8.x4.shared.b16 {%0,%1,%2,%3}, [%4];"
                 : "=r"(r[0]), "=r"(r[1]), "=r"(r[2]), "=r"(r[3]) : "r"(addr));
}
__device__ __forceinline__ void ldsm2t(uint32_t addr, uint32_t* r) {
    asm volatile("ldmatrix.sync.aligned.m8n8.x2.trans.shared.b16 {%0,%1}, [%2];"
                 : "=r"(r[0]), "=r"(r[1]) : "r"(addr));
}
__device__ __forceinline__ void mma16816(float* c, const uint32_t* a, const uint32_t* b) {
    asm volatile(
        "mma.sync.aligned.m16n8k16.row.col.f32.bf16.bf16.f32 "
        "{%0,%1,%2,%3}, {%4,%5,%6,%7}, {%8,%9}, {%0,%1,%2,%3};"
        : "+f"(c[0]), "+f"(c[1]), "+f"(c[2]), "+f"(c[3])
        : "r"(a[0]), "r"(a[1]), "r"(a[2]), "r"(a[3]), "r"(b[0]), "r"(b[1]));
}
__device__ __forceinline__ void mma16816h(float* c, const uint32_t* a, const uint32_t* b) {
    asm volatile(
        "mma.sync.aligned.m16n8k16.row.col.f32.f16.f16.f32 "
        "{%0,%1,%2,%3}, {%4,%5,%6,%7}, {%8,%9}, {%0,%1,%2,%3};"
        : "+f"(c[0]), "+f"(c[1]), "+f"(c[2]), "+f"(c[3])
        : "r"(a[0]), "r"(a[1]), "r"(a[2]), "r"(a[3]), "r"(b[0]), "r"(b[1]));
}
#define CP_ASYNC16(dst, src) \
    asm volatile("cp.async.ca.shared.global [%0], [%1], 16;" :: "r"(dst), "l"(src) : "memory")
#define CP_COMMIT  asm volatile("cp.async.commit_group;" ::: "memory")
#define CP_WAIT0   asm volatile("cp.async.wait_group 0;" ::: "memory")
#define NBAR_SYNC(id)   asm volatile("bar.sync %0, 256;" :: "r"(id) : "memory")
#define NBAR_ARRIVE(id) asm volatile("bar.arrive %0, 256;" :: "r"(id) : "memory")
// barrier ids: FULL0=1 FULL1=2 EMPTY0=3 EMPTY1=4

__device__ __forceinline__ uint32_t sw128(uint32_t o) { return o ^ ((o >> 3) & 0x70); }

// split 4 floats -> main bf16x2 pair + residual bf16x2 pair
__device__ __forceinline__ void split4(float4 v, uint32_t& m0, uint32_t& m1,
                                       uint32_t& r0, uint32_t& r1) {
    asm("cvt.rn.bf16x2.f32 %0, %1, %2;" : "=r"(m0) : "f"(v.y), "f"(v.x));
    asm("cvt.rn.bf16x2.f32 %0, %1, %2;" : "=r"(m1) : "f"(v.w), "f"(v.z));
    float e0 = v.x - __uint_as_float(m0 << 16);
    float e1 = v.y - __uint_as_float(m0 & 0xffff0000u);
    float e2 = v.z - __uint_as_float(m1 << 16);
    float e3 = v.w - __uint_as_float(m1 & 0xffff0000u);
    asm("cvt.rn.bf16x2.f32 %0, %1, %2;" : "=r"(r0) : "f"(e1), "f"(e0));
    asm("cvt.rn.bf16x2.f32 %0, %1, %2;" : "=r"(r1) : "f"(e3), "f"(e2));
}

// ---------------- K_nop: filler so ncu's fixed launch index hits k_gemm ----
__global__ void k_nop() {}

// ---------------- K0: pre-split W into bf16 main + residual (chunk-major) ----
__global__ void k_wsplit(const float* __restrict__ w) {
    int t = blockIdx.x * blockDim.x + threadIdx.x;   // 49152 threads, 8 floats each
    int row = t / 384;
    int kq = t - row * 384;       // k/8
    int chunk = kq >> 3;
    int piece = kq & 7;
    int out = chunk * 1024 + row * 8 + piece;
    const float* src = w + (size_t)row * Kk + kq * 8;
    float4 u = *(const float4*)src;
    float4 v = *(const float4*)(src + 4);
    uint32_t m0, m1, m2, m3, r0, r1, r2, r3;
    split4(u, m0, m1, r0, r1);
    split4(v, m2, m3, r2, r3);
    g_w0u[out] = make_uint4(m0, m1, m2, m3);
    g_w1u[out] = make_uint4(r0, r1, r2, r3);
}

// ---------------- K1: warp-specialized HMMA GEMM (bf16 3-term split) -------
// CTA tile 128x128. Warps 0-3 compute (64x64 each), warps 4-7 produce.
// Stage: A0,A1,B0,B1 each 16KB (128 rows x 128B SW128) = 64KB; 2 stages.
#define ST_SZ 65536
#define OA0 0
#define OA1 16384
#define OB0 32768
#define OB1 49152
#define GEMM_SMEM (1024 + 2 * ST_SZ)

__global__ void __launch_bounds__(256, 1)
k_gemm(const float* __restrict__ sig, const float* __restrict__ mem,
       const float* __restrict__ bias) {
    extern __shared__ char smraw[];
    uint32_t sb = smem_u32(smraw);
    uint32_t ab = (sb + 1023) & ~1023u;
    char* sm = smraw + (ab - sb);

    int tid = threadIdx.x;
    int wid = tid >> 5, lane = tid & 31;

    int bm = blockIdx.x * 128;
    const float* X = (bm < 8192) ? sig : mem;
    int rb = (bm < 8192) ? bm : bm - 8192;

    if (wid >= 4) {
        // ================= PRODUCER =================
        int pt = tid - 128;
        int prow = pt >> 4;        // 0..7
        int pf4 = pt & 15;         // k-quarter (4 floats)
        const float* Xb = X + (size_t)rb * Kk + pf4 * 4;

        for (int c = 0; c < NCHUNK; c++) {
            int s = c & 1;
            uint32_t base = ab + s * ST_SZ;
            char* smA0 = sm + s * ST_SZ + OA0;
            char* smA1 = sm + s * ST_SZ + OA1;
            if (c >= 2) NBAR_SYNC(3 + s);

            // W: fully coalesced cp.async from chunk-major layout
            const uint4* w0c = g_w0u + c * 1024;
            const uint4* w1c = g_w1u + c * 1024;
#pragma unroll
            for (int q = 0; q < 8; q++) {
                int idx = q * 128 + pt;
                uint32_t off = sw128((uint32_t)(idx >> 3) * 128 + (idx & 7) * 16);
                CP_ASYNC16(base + OB0 + off, w0c + idx);
                CP_ASYNC16(base + OB1 + off, w1c + idx);
            }
            CP_COMMIT;

            // A: LDG (coalesced 256B rows) -> split -> STS, 2 batches of 8 rows
            const float* src = Xb + c * 64;
#pragma unroll
            for (int batch = 0; batch < 2; batch++) {
                float4 v[8];
#pragma unroll
                for (int i = 0; i < 8; i++) {
                    int r = (batch * 8 + i) * 8 + prow;
                    v[i] = *(const float4*)(src + (size_t)r * Kk);
                }
#pragma unroll
                for (int i = 0; i < 8; i++) {
                    int r = (batch * 8 + i) * 8 + prow;
                    uint32_t o = sw128((uint32_t)r * 128 + pf4 * 8);
                    uint32_t m0, m1, r0, r1;
                    split4(v[i], m0, m1, r0, r1);
                    *(uint2*)(smA0 + o) = make_uint2(m0, m1);
                    *(uint2*)(smA1 + o) = make_uint2(r0, r1);
                }
            }
            CP_WAIT0;
            asm volatile("membar.cta;" ::: "memory");
            NBAR_ARRIVE(1 + s);
        }
    } else {
        // ================= CONSUMER =================
        int mrow = (wid >> 1) * 64;
        int ncolw = (wid & 1) * 64;

        float acc[4][8][4];
#pragma unroll
        for (int a = 0; a < 4; a++)
#pragma unroll
            for (int b = 0; b < 8; b++)
#pragma unroll
                for (int c = 0; c < 4; c++) acc[a][b][c] = 0.f;

        uint32_t arow_off[4], brow_off[4];
#pragma unroll
        for (int mi = 0; mi < 4; mi++)
            arow_off[mi] = (uint32_t)(mrow + mi * 16 + (lane & 15)) * 128 + ((lane >> 4) << 4);
#pragma unroll
        for (int p = 0; p < 4; p++)
            brow_off[p] = (uint32_t)(ncolw + p * 16 + (lane & 7) + ((lane >> 4) << 3)) * 128
                          + (((lane >> 3) & 1) << 4);

        for (int c = 0; c < NCHUNK; c++) {
            int s = c & 1;
            uint32_t base = ab + s * ST_SZ;
            NBAR_SYNC(1 + s);
#pragma unroll
            for (int j = 0; j < 4; j++) {
                uint32_t fa0[4][4], fa1[4][4], fb0[4][4], fb1[4][4];
#pragma unroll
                for (int mi = 0; mi < 4; mi++) {
                    uint32_t off = sw128(arow_off[mi] + j * 32);
                    ldsm4(base + OA0 + off, fa0[mi]);
                    ldsm4(base + OA1 + off, fa1[mi]);
                }
#pragma unroll
                for (int p = 0; p < 4; p++) {
                    uint32_t off = sw128(brow_off[p] + j * 32);
                    ldsm4(base + OB0 + off, fb0[p]);
                    ldsm4(base + OB1 + off, fb1[p]);
                }
                // term-major: 32 independent accumulators between same-acc MMAs
#pragma unroll
                for (int mi = 0; mi < 4; mi++)
#pragma unroll
                    for (int p = 0; p < 4; p++)
#pragma unroll
                        for (int hh = 0; hh < 2; hh++)
                            mma16816(acc[mi][2 * p + hh], fa0[mi], &fb0[p][2 * hh]);
#pragma unroll
                for (int mi = 0; mi < 4; mi++)
#pragma unroll
                    for (int p = 0; p < 4; p++)
#pragma unroll
                        for (int hh = 0; hh < 2; hh++)
                            mma16816(acc[mi][2 * p + hh], fa1[mi], &fb0[p][2 * hh]);
#pragma unroll
                for (int mi = 0; mi < 4; mi++)
#pragma unroll
                    for (int p = 0; p < 4; p++)
#pragma unroll
                        for (int hh = 0; hh < 2; hh++)
                            mma16816(acc[mi][2 * p + hh], fa0[mi], &fb1[p][2 * hh]);
            }
            NBAR_ARRIVE(3 + s);
        }

        // epilogue: +bias, store to g_embed
        int g = lane >> 2, t4 = lane & 3;
#pragma unroll
        for (int mi = 0; mi < 4; mi++) {
            int row0 = bm + mrow + mi * 16 + g;
#pragma unroll
            for (int tn = 0; tn < 8; tn++) {
                int col = ncolw + tn * 8 + 2 * t4;
                float bx = __ldg(&bias[col]);
                float by = __ldg(&bias[col + 1]);
                float2 o0 = make_float2(acc[mi][tn][0] + bx, acc[mi][tn][1] + by);
                float2 o1 = make_float2(acc[mi][tn][2] + bx, acc[mi][tn][3] + by);
                *(float2*)&g_embed[(size_t)row0 * Ee + col] = o0;
                *(float2*)&g_embed[(size_t)(row0 + 8) * Ee + col] = o1;
            }
        }
    }
}

// ---------------- K2: BN partial sums (deterministic) ----------------
__global__ void k_bn_stats() {
    int e = threadIdx.x;
    int chunk = blockIdx.x;      // 0..31
    int half = blockIdx.y;
    int row0 = half * 8192 + chunk * 256;
    float s = 0.f, sq = 0.f;
#pragma unroll 4
    for (int r = 0; r < 256; r++) {
        float v = g_embed[(size_t)(row0 + r) * Ee + e];
        s += v;
        sq += v * v;
    }
    g_psum[(half * 32 + chunk) * Ee + e] = s;
    g_psumsq[(half * 32 + chunk) * Ee + e] = sq;
}

// ---------------- K4: banded sim + softmax (BN finalize + apply folded) ----
__global__ void k_attn(const float* __restrict__ gamma, const float* __restrict__ beta,
                       float* __restrict__ out_attn) {
    __shared__ float s_et[38 * 129];
    __shared__ float s_ex[8 * 128];
    __shared__ float s_band[8][32];
    __shared__ float s_sc[256], s_sh[256];
    int i0 = blockIdx.x * 8;
    int b = blockIdx.y;
    int jmin = max(0, i0 - HALF_WIN);
    int jmax = min(Nn - 1, i0 + 7 + HALF_WIN);
    int nj = jmax - jmin + 1;
    int tid = threadIdx.x;

    {
        int half = tid >> 7;
        int e = tid & 127;
        float s = 0.f, sq = 0.f;
#pragma unroll
        for (int c = 0; c < 32; c++) {
            s += g_psum[(half * 32 + c) * Ee + e];
            sq += g_psumsq[(half * 32 + c) * Ee + e];
        }
        float mean = s / 8192.f;
        float var = sq / 8192.f - mean * mean;
        float rstd = rsqrtf(var + 1e-5f);
        float sc = rstd * __ldg(&gamma[e]);
        s_sc[tid] = sc;
        s_sh[tid] = __ldg(&beta[e]) - mean * sc;
    }
    __syncthreads();

    for (int p = tid; p < nj * 128; p += 256) {
        int jr = p >> 7, k = p & 127;
        float v = g_embed[(size_t)(8192 + b * Nn + jmin + jr) * Ee + k] * s_sc[128 + k] + s_sh[128 + k];
        s_et[jr * 129 + k] = (v >= 0.f) ? v : 0.1f * v;
    }
    for (int p = tid; p < 8 * 128; p += 256) {
        int r = p >> 7, k = p & 127;
        float v = g_embed[(size_t)(b * Nn + i0 + r) * Ee + k] * s_sc[k] + s_sh[k];
        s_ex[r * 128 + k] = (v >= 0.f) ? v : 0.1f * v;
    }
    __syncthreads();

    int w = tid >> 5, lane = tid & 31;
    int i = i0 + w;
    int j0 = max(0, i - HALF_WIN);
    int j1 = min(Nn - 1, i + HALF_WIN);
    int width = j1 - j0 + 1;

    float sim = -1e30f;
    if (lane < width) {
        int jr = j0 + lane - jmin;
        float acc = 0.f;
        const float* ex = &s_ex[w * 128];
        const float* et = &s_et[jr * 129];
#pragma unroll 8
        for (int k = 0; k < 128; k++) acc += ex[k] * et[k];
        sim = acc;
    }
    float mx = sim;
#pragma unroll
    for (int o = 16; o; o >>= 1) mx = fmaxf(mx, __shfl_xor_sync(0xffffffffu, mx, o));
    float ev = (lane < width) ? expf(sim - mx) : 0.f;
    float sum = ev;
#pragma unroll
    for (int o = 16; o; o >>= 1) sum += __shfl_xor_sync(0xffffffffu, sum, o);
    float a = ev / sum;
    s_band[w][lane] = (lane < width) ? a : 0.f;
    if (lane < width) g_attn_band[(b * Nn + i) * 32 + lane] = a;
    __syncwarp();

    float* rowp = out_attn + ((size_t)(b * Nn + i)) * Nn;
#pragma unroll
    for (int t = 0; t < 16; t++) {
        int j4 = (t * 32 + lane) * 4;
        float4 o = make_float4(0.f, 0.f, 0.f, 0.f);
        if (j4 + 3 >= j0 && j4 <= j1) {
#pragma unroll
            for (int q = 0; q < 4; q++) {
                int j = j4 + q;
                if (j >= j0 && j <= j1) ((float*)&o)[q] = s_band[w][j - j0];
            }
        }
        *(float4*)&rowp[j4] = o;
    }
}

// ---------------- K5: banded attn @ mem via fp16 HMMA + blend --------------
__global__ void __launch_bounds__(256)
k_memw(const float* __restrict__ sig, const float* __restrict__ mem,
       float* __restrict__ out_mem) {
    __shared__ __half s_a0[16][56];
    __shared__ __half s_a1[16][56];
    __shared__ __half s_m[48][264];
    __shared__ float s_out[16][256];
    int i0 = blockIdx.x * 16;
    int fc = blockIdx.y * 256;
    int b = blockIdx.z;
    int tid = threadIdx.x;
    int jmin = max(0, i0 - HALF_WIN);
    int jmax = min(Nn - 1, i0 + 15 + HALF_WIN);
    int nj = jmax - jmin + 1; // <= 46

    for (int p = tid; p < 16 * 28; p += 256) {
        ((uint32_t*)s_a0)[p] = 0u;
        ((uint32_t*)s_a1)[p] = 0u;
    }
    __syncthreads();
    for (int q = tid; q < 16 * 32; q += 256) {
        int r = q >> 5, l = q & 31;
        int i = i0 + r;
        int j0 = max(0, i - HALF_WIN);
        int j1 = min(Nn - 1, i + HALF_WIN);
        if (l <= j1 - j0) {
            float a = g_attn_band[(b * Nn + i) * 32 + l];
            __half a0 = __float2half_rn(a);
            float res = a - __half2float(a0);
            s_a0[r][j0 - jmin + l] = a0;
            s_a1[r][j0 - jmin + l] = __float2half_rn(res);
        }
    }
    for (int p = tid; p < 48 * 64; p += 256) {
        int row = p >> 6, f4 = (p & 63) * 4;
        __half2 h0, h1;
        if (row < nj) {
            float4 v = *(const float4*)&mem[(size_t)(b * Nn + jmin + row) * Kk + fc + f4];
            h0 = __floats2half2_rn(v.x, v.y);
            h1 = __floats2half2_rn(v.z, v.w);
        } else {
            h0 = __floats2half2_rn(0.f, 0.f);
            h1 = h0;
        }
        *(__half2*)&s_m[row][f4] = h0;
        *(__half2*)&s_m[row][f4 + 2] = h1;
    }
    __syncthreads();

    int wid = tid >> 5, lane = tid & 31;
    uint32_t a0base = smem_u32(&s_a0[0][0]);
    uint32_t a1base = smem_u32(&s_a1[0][0]);
    uint32_t mbase = smem_u32(&s_m[0][0]);

    float acc[4][4];
#pragma unroll
    for (int t = 0; t < 4; t++)
#pragma unroll
        for (int c = 0; c < 4; c++) acc[t][c] = 0.f;

#pragma unroll
    for (int ks = 0; ks < 3; ks++) {
        uint32_t fa0[4], fa1[4];
        {
            uint32_t row = lane & 15;
            uint32_t coloff = ks * 16 + (lane >> 4) * 8;
            ldsm4(a0base + (row * 56 + coloff) * 2, fa0);
            ldsm4(a1base + (row * 56 + coloff) * 2, fa1);
        }
#pragma unroll
        for (int t = 0; t < 4; t++) {
            uint32_t ncol = (wid * 4 + t) * 8;
            uint32_t krow = ks * 16 + (lane & 15);
            uint32_t fb[2];
            ldsm2t(mbase + (krow * 264 + ncol) * 2, fb);
            mma16816h(acc[t], fa0, fb);
            mma16816h(acc[t], fa1, fb);
        }
    }

    int g = lane >> 2, c2 = (lane & 3) * 2;
#pragma unroll
    for (int t = 0; t < 4; t++) {
        int cb = wid * 32 + t * 8 + c2;
        s_out[g][cb] = acc[t][0];
        s_out[g][cb + 1] = acc[t][1];
        s_out[g + 8][cb] = acc[t][2];
        s_out[g + 8][cb + 1] = acc[t][3];
    }
    __syncthreads();

    for (int p = tid; p < 16 * 64; p += 256) {
        int r = p >> 6, f4 = (p & 63) * 4;
        size_t base = (size_t)(b * Nn + i0 + r) * Kk + fc + f4;
        float4 sg = *(const float4*)&sig[base];
        float4 mv = *(float4*)&s_out[r][f4];
        float4 o;
        o.x = 0.5f * sg.x + 0.5f * mv.x;
        o.y = 0.5f * sg.y + 0.5f * mv.y;
        o.z = 0.5f * sg.z + 0.5f * mv.z;
        o.w = 0.5f * sg.w + 0.5f * mv.w;
        *(float4*)&out_mem[base] = o;
    }
}

// ---------------- launch ----------------
extern "C" void kernel_launch(void* const* d_in, const int* in_sizes, int n_in,
                              void* d_out, int out_size) {
    const float* sig   = (const float*)d_in[0];
    const float* mem   = (const float*)d_in[1];
    const float* w     = (const float*)d_in[2];
    const float* bias  = (const float*)d_in[3];
    const float* gamma = (const float*)d_in[4];
    const float* beta  = (const float*)d_in[5];
    float* out_mem  = (float*)d_out;
    float* out_attn = (float*)d_out + (size_t)Bsz * Nn * Kk;

    static bool attr_done = false;
    if (!attr_done) {
        cudaFuncSetAttribute(k_gemm, cudaFuncAttributeMaxDynamicSharedMemorySize, GEMM_SMEM);
        attr_done = true;
    }

    k_wsplit<<<192, 256>>>(w);       // launch 0
    k_nop<<<1, 32>>>();              // launch 1 (filler)
    k_nop<<<1, 32>>>();              // launch 2 (filler)
    k_gemm<<<Mm / 128, 256, GEMM_SMEM>>>(sig, mem, bias);   // launch 3 -> ncu target
    k_bn_stats<<<dim3(32, 2), 128>>>();
    k_attn<<<dim3(Nn / 8, Bsz), 256>>>(gamma, beta, out_attn);
    k_memw<<<dim3(Nn / 16, 12, Bsz), 256>>>(sig, mem, out_mem);
}

// round 9
// speedup vs baseline: 1.6258x; 1.1493x over previous
#include <cuda_runtime.h>
#include <cuda_fp16.h>
#include <math.h>
#include <stdint.h>

#define Bsz 4
#define Nn 2048
#define Ee 128
#define Kk 3072            // C*P
#define Mm 16384           // 2*B*N rows (sig half then mem half)
#define HALF_WIN 15
#define NCHUNK 48          // 3072 / 64

// ---------------- scratch ----------------
__device__ float g_embed[Mm * Ee];           // pre-BN y = conv(x)+bias
__device__ float g_psum[128 * Ee];           // per-GEMM-CTA column sums
__device__ float g_psumsq[128 * Ee];
__device__ float g_attn_band[Bsz * Nn * 32];
__device__ uint4 g_w0u[49152];               // W main bf16, CHUNK-major [48][128 rows][8 uint4]
__device__ uint4 g_w1u[49152];               // W residual bf16, same layout

// ---------------- helpers ----------------
__device__ __forceinline__ uint32_t smem_u32(const void* p) {
    uint32_t a;
    asm("{ .reg .u64 t; cvta.to.shared.u64 t, %1; cvt.u32.u64 %0, t; }" : "=r"(a) : "l"(p));
    return a;
}
__device__ __forceinline__ void ldsm4(uint32_t addr, uint32_t* r) {
    asm volatile("ldmatrix.sync.aligned.m8n8.x4.shared.b16 {%0,%1,%2,%3}, [%4];"
                 : "=r"(r[0]), "=r"(r[1]), "=r"(r[2]), "=r"(r[3]) : "r"(addr));
}
__device__ __forceinline__ void ldsm2t(uint32_t addr, uint32_t* r) {
    asm volatile("ldmatrix.sync.aligned.m8n8.x2.trans.shared.b16 {%0,%1}, [%2];"
                 : "=r"(r[0]), "=r"(r[1]) : "r"(addr));
}
__device__ __forceinline__ void mma16816(float* c, const uint32_t* a, const uint32_t* b) {
    asm volatile(
        "mma.sync.aligned.m16n8k16.row.col.f32.bf16.bf16.f32 "
        "{%0,%1,%2,%3}, {%4,%5,%6,%7}, {%8,%9}, {%0,%1,%2,%3};"
        : "+f"(c[0]), "+f"(c[1]), "+f"(c[2]), "+f"(c[3])
        : "r"(a[0]), "r"(a[1]), "r"(a[2]), "r"(a[3]), "r"(b[0]), "r"(b[1]));
}
__device__ __forceinline__ void mma16816h(float* c, const uint32_t* a, const uint32_t* b) {
    asm volatile(
        "mma.sync.aligned.m16n8k16.row.col.f32.f16.f16.f32 "
        "{%0,%1,%2,%3}, {%4,%5,%6,%7}, {%8,%9}, {%0,%1,%2,%3};"
        : "+f"(c[0]), "+f"(c[1]), "+f"(c[2]), "+f"(c[3])
        : "r"(a[0]), "r"(a[1]), "r"(a[2]), "r"(a[3]), "r"(b[0]), "r"(b[1]));
}
#define CP_ASYNC16(dst, src) \
    asm volatile("cp.async.ca.shared.global [%0], [%1], 16;" :: "r"(dst), "l"(src) : "memory")
#define CP_COMMIT  asm volatile("cp.async.commit_group;" ::: "memory")
#define CP_WAIT0   asm volatile("cp.async.wait_group 0;" ::: "memory")
#define NBAR_SYNC(id)   asm volatile("bar.sync %0, 256;" :: "r"(id) : "memory")
#define NBAR_ARRIVE(id) asm volatile("bar.arrive %0, 256;" :: "r"(id) : "memory")

__device__ __forceinline__ uint32_t sw128(uint32_t o) { return o ^ ((o >> 3) & 0x70); }

__device__ __forceinline__ void split4(float4 v, uint32_t& m0, uint32_t& m1,
                                       uint32_t& r0, uint32_t& r1) {
    asm("cvt.rn.bf16x2.f32 %0, %1, %2;" : "=r"(m0) : "f"(v.y), "f"(v.x));
    asm("cvt.rn.bf16x2.f32 %0, %1, %2;" : "=r"(m1) : "f"(v.w), "f"(v.z));
    float e0 = v.x - __uint_as_float(m0 << 16);
    float e1 = v.y - __uint_as_float(m0 & 0xffff0000u);
    float e2 = v.z - __uint_as_float(m1 << 16);
    float e3 = v.w - __uint_as_float(m1 & 0xffff0000u);
    asm("cvt.rn.bf16x2.f32 %0, %1, %2;" : "=r"(r0) : "f"(e1), "f"(e0));
    asm("cvt.rn.bf16x2.f32 %0, %1, %2;" : "=r"(r1) : "f"(e3), "f"(e2));
}

// ---------------- K_nop: filler so ncu's fixed launch index hits k_gemm ----
__global__ void k_nop() {}

// ---------------- K0: pre-split W into bf16 main + residual (chunk-major) ----
__global__ void k_wsplit(const float* __restrict__ w) {
    int t = blockIdx.x * blockDim.x + threadIdx.x;
    int row = t / 384;
    int kq = t - row * 384;
    int chunk = kq >> 3;
    int piece = kq & 7;
    int out = chunk * 1024 + row * 8 + piece;
    const float* src = w + (size_t)row * Kk + kq * 8;
    float4 u = *(const float4*)src;
    float4 v = *(const float4*)(src + 4);
    uint32_t m0, m1, m2, m3, r0, r1, r2, r3;
    split4(u, m0, m1, r0, r1);
    split4(v, m2, m3, r2, r3);
    g_w0u[out] = make_uint4(m0, m1, m2, m3);
    g_w1u[out] = make_uint4(r0, r1, r2, r3);
}

// ---------------- K1: warp-specialized HMMA GEMM + fused BN stats -----------
#define ST_SZ 65536
#define OA0 0
#define OA1 16384
#define OB0 32768
#define OB1 49152
#define GEMM_SMEM (1024 + 2 * ST_SZ + 2048)

__global__ void __launch_bounds__(256, 1)
k_gemm(const float* __restrict__ sig, const float* __restrict__ mem,
       const float* __restrict__ bias) {
    extern __shared__ char smraw[];
    uint32_t sb = smem_u32(smraw);
    uint32_t ab = (sb + 1023) & ~1023u;
    char* sm = smraw + (ab - sb);

    int tid = threadIdx.x;
    int wid = tid >> 5, lane = tid & 31;

    int bm = blockIdx.x * 128;
    const float* X = (bm < 8192) ? sig : mem;
    int rb = (bm < 8192) ? bm : bm - 8192;

    float* bn_s = (float*)(sm + 2 * ST_SZ);        // [4][8][8]
    float* bn_q = bn_s + 256;

    if (wid >= 4) {
        // ================= PRODUCER =================
        int pt = tid - 128;
        int prow = pt >> 4;
        int pf4 = pt & 15;
        const float* Xb = X + (size_t)rb * Kk + pf4 * 4;

        for (int c = 0; c < NCHUNK; c++) {
            int s = c & 1;
            uint32_t base = ab + s * ST_SZ;
            char* smA0 = sm + s * ST_SZ + OA0;
            char* smA1 = sm + s * ST_SZ + OA1;
            if (c >= 2) NBAR_SYNC(3 + s);

            const uint4* w0c = g_w0u + c * 1024;
            const uint4* w1c = g_w1u + c * 1024;
#pragma unroll
            for (int q = 0; q < 8; q++) {
                int idx = q * 128 + pt;
                uint32_t off = sw128((uint32_t)(idx >> 3) * 128 + (idx & 7) * 16);
                CP_ASYNC16(base + OB0 + off, w0c + idx);
                CP_ASYNC16(base + OB1 + off, w1c + idx);
            }
            CP_COMMIT;

            const float* src = Xb + c * 64;
#pragma unroll
            for (int batch = 0; batch < 2; batch++) {
                float4 v[8];
#pragma unroll
                for (int i = 0; i < 8; i++) {
                    int r = (batch * 8 + i) * 8 + prow;
                    v[i] = *(const float4*)(src + (size_t)r * Kk);
                }
#pragma unroll
                for (int i = 0; i < 8; i++) {
                    int r = (batch * 8 + i) * 8 + prow;
                    uint32_t o = sw128((uint32_t)r * 128 + pf4 * 8);
                    uint32_t m0, m1, r0, r1;
                    split4(v[i], m0, m1, r0, r1);
                    *(uint2*)(smA0 + o) = make_uint2(m0, m1);
                    *(uint2*)(smA1 + o) = make_uint2(r0, r1);
                }
            }
            CP_WAIT0;
            asm volatile("membar.cta;" ::: "memory");
            NBAR_ARRIVE(1 + s);
        }
    } else {
        // ================= CONSUMER =================
        int mrow = (wid >> 1) * 64;
        int ncolw = (wid & 1) * 64;

        float acc[4][8][4];
#pragma unroll
        for (int a = 0; a < 4; a++)
#pragma unroll
            for (int b = 0; b < 8; b++)
#pragma unroll
                for (int c = 0; c < 4; c++) acc[a][b][c] = 0.f;

        uint32_t arow_off[4], brow_off[4];
#pragma unroll
        for (int mi = 0; mi < 4; mi++)
            arow_off[mi] = (uint32_t)(mrow + mi * 16 + (lane & 15)) * 128 + ((lane >> 4) << 4);
#pragma unroll
        for (int p = 0; p < 4; p++)
            brow_off[p] = (uint32_t)(ncolw + p * 16 + (lane & 7) + ((lane >> 4) << 3)) * 128
                          + (((lane >> 3) & 1) << 4);

        for (int c = 0; c < NCHUNK; c++) {
            int s = c & 1;
            uint32_t base = ab + s * ST_SZ;
            NBAR_SYNC(1 + s);
#pragma unroll
            for (int j = 0; j < 4; j++) {
                uint32_t fa0[4][4], fa1[4][4], fb0[4][4], fb1[4][4];
#pragma unroll
                for (int mi = 0; mi < 4; mi++) {
                    uint32_t off = sw128(arow_off[mi] + j * 32);
                    ldsm4(base + OA0 + off, fa0[mi]);
                    ldsm4(base + OA1 + off, fa1[mi]);
                }
#pragma unroll
                for (int p = 0; p < 4; p++) {
                    uint32_t off = sw128(brow_off[p] + j * 32);
                    ldsm4(base + OB0 + off, fb0[p]);
                    ldsm4(base + OB1 + off, fb1[p]);
                }
#pragma unroll
                for (int mi = 0; mi < 4; mi++)
#pragma unroll
                    for (int p = 0; p < 4; p++)
#pragma unroll
                        for (int hh = 0; hh < 2; hh++)
                            mma16816(acc[mi][2 * p + hh], fa0[mi], &fb0[p][2 * hh]);
#pragma unroll
                for (int mi = 0; mi < 4; mi++)
#pragma unroll
                    for (int p = 0; p < 4; p++)
#pragma unroll
                        for (int hh = 0; hh < 2; hh++)
                            mma16816(acc[mi][2 * p + hh], fa1[mi], &fb0[p][2 * hh]);
#pragma unroll
                for (int mi = 0; mi < 4; mi++)
#pragma unroll
                    for (int p = 0; p < 4; p++)
#pragma unroll
                        for (int hh = 0; hh < 2; hh++)
                            mma16816(acc[mi][2 * p + hh], fa0[mi], &fb1[p][2 * hh]);
            }
            NBAR_ARRIVE(3 + s);
        }

        // epilogue: +bias, store, and accumulate BN column stats
        int g = lane >> 2, t4 = lane & 3;
#pragma unroll
        for (int tn = 0; tn < 8; tn++) {
            int col = ncolw + tn * 8 + 2 * t4;
            float bx = __ldg(&bias[col]);
            float by = __ldg(&bias[col + 1]);
            float sx = 0.f, sy = 0.f, qx = 0.f, qy = 0.f;
#pragma unroll
            for (int mi = 0; mi < 4; mi++) {
                int row0 = bm + mrow + mi * 16 + g;
                float o0 = acc[mi][tn][0] + bx;
                float o1 = acc[mi][tn][1] + by;
                float o2 = acc[mi][tn][2] + bx;
                float o3 = acc[mi][tn][3] + by;
                *(float2*)&g_embed[(size_t)row0 * Ee + col] = make_float2(o0, o1);
                *(float2*)&g_embed[(size_t)(row0 + 8) * Ee + col] = make_float2(o2, o3);
                sx += o0 + o2; sy += o1 + o3;
                qx += o0 * o0 + o2 * o2; qy += o1 * o1 + o3 * o3;
            }
#pragma unroll
            for (int msk = 4; msk < 32; msk <<= 1) {
                sx += __shfl_xor_sync(0xffffffffu, sx, msk);
                sy += __shfl_xor_sync(0xffffffffu, sy, msk);
                qx += __shfl_xor_sync(0xffffffffu, qx, msk);
                qy += __shfl_xor_sync(0xffffffffu, qy, msk);
            }
            if ((lane >> 2) == 0) {
                bn_s[(wid * 8 + tn) * 8 + 2 * t4] = sx;
                bn_s[(wid * 8 + tn) * 8 + 2 * t4 + 1] = sy;
                bn_q[(wid * 8 + tn) * 8 + 2 * t4] = qx;
                bn_q[(wid * 8 + tn) * 8 + 2 * t4 + 1] = qy;
            }
        }
    }
    __syncthreads();
    if (tid < 128) {
        int e = tid;
        int tn = (e & 63) >> 3, k = e & 7;
        int w0 = (e >> 6);             // 0 or 1; partner w0+2
        float s = bn_s[((w0)*8 + tn) * 8 + k] + bn_s[((w0 + 2) * 8 + tn) * 8 + k];
        float q = bn_q[((w0)*8 + tn) * 8 + k] + bn_q[((w0 + 2) * 8 + tn) * 8 + k];
        g_psum[blockIdx.x * 128 + e] = s;
        g_psumsq[blockIdx.x * 128 + e] = q;
    }
}

// ---------------- K4: banded sim + softmax (BN finalize + apply folded) ----
__global__ void k_attn(const float* __restrict__ gamma, const float* __restrict__ beta,
                       float* __restrict__ out_attn) {
    __shared__ float s_et[38 * 129];
    __shared__ float s_ex[8 * 128];
    __shared__ float s_band[8][32];
    __shared__ float s_sc[256], s_sh[256];
    int i0 = blockIdx.x * 8;
    int b = blockIdx.y;
    int jmin = max(0, i0 - HALF_WIN);
    int jmax = min(Nn - 1, i0 + 7 + HALF_WIN);
    int nj = jmax - jmin + 1;
    int tid = threadIdx.x;

    {
        int half = tid >> 7;
        int e = tid & 127;
        float s = 0.f, sq = 0.f;
#pragma unroll 8
        for (int c = 0; c < 64; c++) {
            s += g_psum[(half * 64 + c) * Ee + e];
            sq += g_psumsq[(half * 64 + c) * Ee + e];
        }
        float mean = s / 8192.f;
        float var = sq / 8192.f - mean * mean;
        float rstd = rsqrtf(var + 1e-5f);
        float sc = rstd * __ldg(&gamma[e]);
        s_sc[tid] = sc;
        s_sh[tid] = __ldg(&beta[e]) - mean * sc;
    }
    __syncthreads();

    for (int p = tid; p < nj * 128; p += 256) {
        int jr = p >> 7, k = p & 127;
        float v = g_embed[(size_t)(8192 + b * Nn + jmin + jr) * Ee + k] * s_sc[128 + k] + s_sh[128 + k];
        s_et[jr * 129 + k] = (v >= 0.f) ? v : 0.1f * v;
    }
    for (int p = tid; p < 8 * 128; p += 256) {
        int r = p >> 7, k = p & 127;
        float v = g_embed[(size_t)(b * Nn + i0 + r) * Ee + k] * s_sc[k] + s_sh[k];
        s_ex[r * 128 + k] = (v >= 0.f) ? v : 0.1f * v;
    }
    __syncthreads();

    int w = tid >> 5, lane = tid & 31;
    int i = i0 + w;
    int j0 = max(0, i - HALF_WIN);
    int j1 = min(Nn - 1, i + HALF_WIN);
    int width = j1 - j0 + 1;

    float sim = -1e30f;
    if (lane < width) {
        int jr = j0 + lane - jmin;
        float acc = 0.f;
        const float* ex = &s_ex[w * 128];
        const float* et = &s_et[jr * 129];
#pragma unroll 8
        for (int k = 0; k < 128; k++) acc += ex[k] * et[k];
        sim = acc;
    }
    float mx = sim;
#pragma unroll
    for (int o = 16; o; o >>= 1) mx = fmaxf(mx, __shfl_xor_sync(0xffffffffu, mx, o));
    float ev = (lane < width) ? expf(sim - mx) : 0.f;
    float sum = ev;
#pragma unroll
    for (int o = 16; o; o >>= 1) sum += __shfl_xor_sync(0xffffffffu, sum, o);
    float a = ev / sum;
    s_band[w][lane] = (lane < width) ? a : 0.f;
    if (lane < width) g_attn_band[(b * Nn + i) * 32 + lane] = a;
    __syncwarp();

    float* rowp = out_attn + ((size_t)(b * Nn + i)) * Nn;
#pragma unroll
    for (int t = 0; t < 16; t++) {
        int j4 = (t * 32 + lane) * 4;
        float4 o = make_float4(0.f, 0.f, 0.f, 0.f);
        if (j4 + 3 >= j0 && j4 <= j1) {
#pragma unroll
            for (int q = 0; q < 4; q++) {
                int j = j4 + q;
                if (j >= j0 && j <= j1) ((float*)&o)[q] = s_band[w][j - j0];
            }
        }
        *(float4*)&rowp[j4] = o;
    }
}

// ---------------- K5: banded attn @ mem via fp16 HMMA, 64-row tiles --------
// block = 64 i-rows x 256 f; K = band union (<=94) padded to 96; 8 warps.
// smem: a0[64][104], a1[64][104] fp16 (13312B each), m[96][264] fp16 (50688B)
#define MW_A0 0
#define MW_A1 13312
#define MW_M  26624
#define MW_SMEM (26624 + 50688 + 256)

__global__ void __launch_bounds__(256, 2)
k_memw(const float* __restrict__ sig, const float* __restrict__ mem,
       float* __restrict__ out_mem) {
    extern __shared__ char smw[];
    uint32_t mwb = smem_u32(smw);
    int i0 = blockIdx.x * 64;
    int fc = blockIdx.y * 256;
    int b = blockIdx.z;
    int tid = threadIdx.x;
    int jmin = max(0, i0 - HALF_WIN);
    int jmax = min(Nn - 1, i0 + 63 + HALF_WIN);
    int nj = jmax - jmin + 1;     // <= 94

    __half* s_a0 = (__half*)(smw + MW_A0);
    __half* s_a1 = (__half*)(smw + MW_A1);
    __half* s_m  = (__half*)(smw + MW_M);

    // zero attn tiles (26624 B = 6656 words)
    for (int p = tid; p < 6656; p += 256) ((uint32_t*)smw)[p] = 0u;
    __syncthreads();

    // fill attn band (fp16 split)
    for (int q = tid; q < 64 * 32; q += 256) {
        int r = q >> 5, l = q & 31;
        int i = i0 + r;
        int j0 = max(0, i - HALF_WIN);
        int j1 = min(Nn - 1, i + HALF_WIN);
        if (l <= j1 - j0) {
            float a = g_attn_band[(b * Nn + i) * 32 + l];
            __half a0 = __float2half_rn(a);
            float res = a - __half2float(a0);
            int col = (j0 - jmin) + l;
            s_a0[r * 104 + col] = a0;
            s_a1[r * 104 + col] = __float2half_rn(res);
        }
    }
    // fill mem tile [96][264], rows >= nj zero
    for (int p = tid; p < 96 * 64; p += 256) {
        int row = p >> 6, f4 = (p & 63) * 4;
        __half2 h0, h1;
        if (row < nj) {
            float4 v = *(const float4*)&mem[(size_t)(b * Nn + jmin + row) * Kk + fc + f4];
            h0 = __floats2half2_rn(v.x, v.y);
            h1 = __floats2half2_rn(v.z, v.w);
        } else {
            h0 = __floats2half2_rn(0.f, 0.f);
            h1 = h0;
        }
        *(__half2*)&s_m[row * 264 + f4] = h0;
        *(__half2*)&s_m[row * 264 + f4 + 2] = h1;
    }
    __syncthreads();

    int wid = tid >> 5, lane = tid & 31;
    uint32_t a0b = mwb + MW_A0;
    uint32_t a1b = mwb + MW_A1;
    uint32_t mb = mwb + MW_M;

    float acc[4][4][4];   // [mi][t][4]
#pragma unroll
    for (int mi = 0; mi < 4; mi++)
#pragma unroll
        for (int t = 0; t < 4; t++)
#pragma unroll
            for (int c = 0; c < 4; c++) acc[mi][t][c] = 0.f;

#pragma unroll
    for (int ks = 0; ks < 6; ks++) {
        uint32_t fa0[4][4], fa1[4][4];
#pragma unroll
        for (int mi = 0; mi < 4; mi++) {
            uint32_t row = mi * 16 + (lane & 15);
            uint32_t col = ks * 16 + ((lane >> 4) << 3);
            ldsm4(a0b + (row * 104 + col) * 2, fa0[mi]);
            ldsm4(a1b + (row * 104 + col) * 2, fa1[mi]);
        }
#pragma unroll
        for (int t = 0; t < 4; t++) {
            uint32_t ncol = (wid * 4 + t) * 8;
            uint32_t krow = ks * 16 + (lane & 15);
            uint32_t fb[2];
            ldsm2t(mb + (krow * 264 + ncol) * 2, fb);
#pragma unroll
            for (int mi = 0; mi < 4; mi++) {
                mma16816h(acc[mi][t], fa0[mi], fb);
                mma16816h(acc[mi][t], fa1[mi], fb);
            }
        }
    }

    // blend + store directly from fragments (32B sectors per 8-lane row group)
    int g = lane >> 2, t4 = lane & 3;
#pragma unroll
    for (int mi = 0; mi < 4; mi++) {
#pragma unroll
        for (int t = 0; t < 4; t++) {
            int col = wid * 32 + t * 8 + 2 * t4;
            int row0 = i0 + mi * 16 + g;
            size_t base0 = (size_t)(b * Nn + row0) * Kk + fc + col;
            size_t base1 = (size_t)(b * Nn + row0 + 8) * Kk + fc + col;
            float2 sg0 = *(const float2*)&sig[base0];
            float2 sg1 = *(const float2*)&sig[base1];
            float2 o0 = make_float2(0.5f * sg0.x + 0.5f * acc[mi][t][0],
                                    0.5f * sg0.y + 0.5f * acc[mi][t][1]);
            float2 o1 = make_float2(0.5f * sg1.x + 0.5f * acc[mi][t][2],
                                    0.5f * sg1.y + 0.5f * acc[mi][t][3]);
            *(float2*)&out_mem[base0] = o0;
            *(float2*)&out_mem[base1] = o1;
        }
    }
}

// ---------------- launch ----------------
extern "C" void kernel_launch(void* const* d_in, const int* in_sizes, int n_in,
                              void* d_out, int out_size) {
    const float* sig   = (const float*)d_in[0];
    const float* mem   = (const float*)d_in[1];
    const float* w     = (const float*)d_in[2];
    const float* bias  = (const float*)d_in[3];
    const float* gamma = (const float*)d_in[4];
    const float* beta  = (const float*)d_in[5];
    float* out_mem  = (float*)d_out;
    float* out_attn = (float*)d_out + (size_t)Bsz * Nn * Kk;

    static bool attr_done = false;
    if (!attr_done) {
        cudaFuncSetAttribute(k_gemm, cudaFuncAttributeMaxDynamicSharedMemorySize, GEMM_SMEM);
        cudaFuncSetAttribute(k_memw, cudaFuncAttributeMaxDynamicSharedMemorySize, MW_SMEM);
        attr_done = true;
    }

    k_wsplit<<<192, 256>>>(w);       // launch 0
    k_nop<<<1, 32>>>();              // launch 1 (filler)
    k_nop<<<1, 32>>>();              // launch 2 (filler)
    k_gemm<<<Mm / 128, 256, GEMM_SMEM>>>(sig, mem, bias);   // launch 3 -> ncu target
    k_attn<<<dim3(Nn / 8, Bsz), 256>>>(gamma, beta, out_attn);
    k_memw<<<dim3(Nn / 64, 12, Bsz), 256, MW_SMEM>>>(sig, mem, out_mem);
}

// round 10
// speedup vs baseline: 1.6350x; 1.0057x over previous
#include <cuda_runtime.h>
#include <cuda_fp16.h>
#include <math.h>
#include <stdint.h>

#define Bsz 4
#define Nn 2048
#define Ee 128
#define Kk 3072            // C*P
#define Mm 16384           // 2*B*N rows (sig half then mem half)
#define HALF_WIN 15
#define NCHUNK 48          // 3072 / 64

// ---------------- scratch ----------------
__device__ float g_embed[Mm * Ee];           // pre-BN y = conv(x)+bias
__device__ float g_psum[128 * Ee];           // per-GEMM-CTA column sums
__device__ float g_psumsq[128 * Ee];
__device__ float g_attn_band[Bsz * Nn * 32];
__device__ uint4 g_w0u[49152];               // W main bf16, CHUNK-major [48][128 rows][8 uint4]
__device__ uint4 g_w1u[49152];               // W residual bf16, same layout

// ---------------- helpers ----------------
__device__ __forceinline__ uint32_t smem_u32(const void* p) {
    uint32_t a;
    asm("{ .reg .u64 t; cvta.to.shared.u64 t, %1; cvt.u32.u64 %0, t; }" : "=r"(a) : "l"(p));
    return a;
}
__device__ __forceinline__ void ldsm4(uint32_t addr, uint32_t* r) {
    asm volatile("ldmatrix.sync.aligned.m8n8.x4.shared.b16 {%0,%1,%2,%3}, [%4];"
                 : "=r"(r[0]), "=r"(r[1]), "=r"(r[2]), "=r"(r[3]) : "r"(addr));
}
__device__ __forceinline__ void ldsm2t(uint32_t addr, uint32_t* r) {
    asm volatile("ldmatrix.sync.aligned.m8n8.x2.trans.shared.b16 {%0,%1}, [%2];"
                 : "=r"(r[0]), "=r"(r[1]) : "r"(addr));
}
__device__ __forceinline__ void mma16816(float* c, const uint32_t* a, const uint32_t* b) {
    asm volatile(
        "mma.sync.aligned.m16n8k16.row.col.f32.bf16.bf16.f32 "
        "{%0,%1,%2,%3}, {%4,%5,%6,%7}, {%8,%9}, {%0,%1,%2,%3};"
        : "+f"(c[0]), "+f"(c[1]), "+f"(c[2]), "+f"(c[3])
        : "r"(a[0]), "r"(a[1]), "r"(a[2]), "r"(a[3]), "r"(b[0]), "r"(b[1]));
}
__device__ __forceinline__ void mma16816h(float* c, const uint32_t* a, const uint32_t* b) {
    asm volatile(
        "mma.sync.aligned.m16n8k16.row.col.f32.f16.f16.f32 "
        "{%0,%1,%2,%3}, {%4,%5,%6,%7}, {%8,%9}, {%0,%1,%2,%3};"
        : "+f"(c[0]), "+f"(c[1]), "+f"(c[2]), "+f"(c[3])
        : "r"(a[0]), "r"(a[1]), "r"(a[2]), "r"(a[3]), "r"(b[0]), "r"(b[1]));
}
#define CP_ASYNC16(dst, src) \
    asm volatile("cp.async.ca.shared.global [%0], [%1], 16;" :: "r"(dst), "l"(src) : "memory")
#define CP_COMMIT  asm volatile("cp.async.commit_group;" ::: "memory")
#define CP_WAIT0   asm volatile("cp.async.wait_group 0;" ::: "memory")
#define NBAR_SYNC(id)   asm volatile("bar.sync %0, 256;" :: "r"(id) : "memory")
#define NBAR_ARRIVE(id) asm volatile("bar.arrive %0, 256;" :: "r"(id) : "memory")
// barrier ids: FULL = 1+s (1..3), EMPTY = 4+s (4..6)

__device__ __forceinline__ uint32_t sw128(uint32_t o) { return o ^ ((o >> 3) & 0x70); }

__device__ __forceinline__ void split4(float4 v, uint32_t& m0, uint32_t& m1,
                                       uint32_t& r0, uint32_t& r1) {
    asm("cvt.rn.bf16x2.f32 %0, %1, %2;" : "=r"(m0) : "f"(v.y), "f"(v.x));
    asm("cvt.rn.bf16x2.f32 %0, %1, %2;" : "=r"(m1) : "f"(v.w), "f"(v.z));
    float e0 = v.x - __uint_as_float(m0 << 16);
    float e1 = v.y - __uint_as_float(m0 & 0xffff0000u);
    float e2 = v.z - __uint_as_float(m1 << 16);
    float e3 = v.w - __uint_as_float(m1 & 0xffff0000u);
    asm("cvt.rn.bf16x2.f32 %0, %1, %2;" : "=r"(r0) : "f"(e1), "f"(e0));
    asm("cvt.rn.bf16x2.f32 %0, %1, %2;" : "=r"(r1) : "f"(e3), "f"(e2));
}

// ---------------- K0: pre-split W into bf16 main + residual (chunk-major) ----
__global__ void k_wsplit(const float* __restrict__ w) {
    int t = blockIdx.x * blockDim.x + threadIdx.x;
    int row = t / 384;
    int kq = t - row * 384;
    int chunk = kq >> 3;
    int piece = kq & 7;
    int out = chunk * 1024 + row * 8 + piece;
    const float* src = w + (size_t)row * Kk + kq * 8;
    float4 u = *(const float4*)src;
    float4 v = *(const float4*)(src + 4);
    uint32_t m0, m1, m2, m3, r0, r1, r2, r3;
    split4(u, m0, m1, r0, r1);
    split4(v, m2, m3, r2, r3);
    g_w0u[out] = make_uint4(m0, m1, m2, m3);
    g_w1u[out] = make_uint4(r0, r1, r2, r3);
}

// ---------------- K1: warp-specialized HMMA GEMM + fused BN stats -----------
// 3-stage pipeline: stage = c % 3
#define ST_SZ 65536
#define OA0 0
#define OA1 16384
#define OB0 32768
#define OB1 49152
#define GEMM_SMEM (1024 + 3 * ST_SZ + 2048)

__global__ void __launch_bounds__(256, 1)
k_gemm(const float* __restrict__ sig, const float* __restrict__ mem,
       const float* __restrict__ bias) {
    extern __shared__ char smraw[];
    uint32_t sb = smem_u32(smraw);
    uint32_t ab = (sb + 1023) & ~1023u;
    char* sm = smraw + (ab - sb);

    int tid = threadIdx.x;
    int wid = tid >> 5, lane = tid & 31;

    int bm = blockIdx.x * 128;
    const float* X = (bm < 8192) ? sig : mem;
    int rb = (bm < 8192) ? bm : bm - 8192;

    float* bn_s = (float*)(sm + 3 * ST_SZ);        // [4][8][8]
    float* bn_q = bn_s + 256;

    if (wid >= 4) {
        // ================= PRODUCER =================
        int pt = tid - 128;
        int prow = pt >> 4;
        int pf4 = pt & 15;
        const float* Xb = X + (size_t)rb * Kk + pf4 * 4;

        int s = 0;
        for (int c = 0; c < NCHUNK; c++) {
            uint32_t base = ab + s * ST_SZ;
            char* smA0 = sm + s * ST_SZ + OA0;
            char* smA1 = sm + s * ST_SZ + OA1;
            if (c >= 3) NBAR_SYNC(4 + s);

            const uint4* w0c = g_w0u + c * 1024;
            const uint4* w1c = g_w1u + c * 1024;
#pragma unroll
            for (int q = 0; q < 8; q++) {
                int idx = q * 128 + pt;
                uint32_t off = sw128((uint32_t)(idx >> 3) * 128 + (idx & 7) * 16);
                CP_ASYNC16(base + OB0 + off, w0c + idx);
                CP_ASYNC16(base + OB1 + off, w1c + idx);
            }
            CP_COMMIT;

            const float* src = Xb + c * 64;
#pragma unroll
            for (int batch = 0; batch < 2; batch++) {
                float4 v[8];
#pragma unroll
                for (int i = 0; i < 8; i++) {
                    int r = (batch * 8 + i) * 8 + prow;
                    v[i] = *(const float4*)(src + (size_t)r * Kk);
                }
#pragma unroll
                for (int i = 0; i < 8; i++) {
                    int r = (batch * 8 + i) * 8 + prow;
                    uint32_t o = sw128((uint32_t)r * 128 + pf4 * 8);
                    uint32_t m0, m1, r0, r1;
                    split4(v[i], m0, m1, r0, r1);
                    *(uint2*)(smA0 + o) = make_uint2(m0, m1);
                    *(uint2*)(smA1 + o) = make_uint2(r0, r1);
                }
            }
            CP_WAIT0;
            asm volatile("membar.cta;" ::: "memory");
            NBAR_ARRIVE(1 + s);
            s = (s == 2) ? 0 : s + 1;
        }
    } else {
        // ================= CONSUMER =================
        int mrow = (wid >> 1) * 64;
        int ncolw = (wid & 1) * 64;

        float acc[4][8][4];
#pragma unroll
        for (int a = 0; a < 4; a++)
#pragma unroll
            for (int b = 0; b < 8; b++)
#pragma unroll
                for (int c = 0; c < 4; c++) acc[a][b][c] = 0.f;

        uint32_t arow_off[4], brow_off[4];
#pragma unroll
        for (int mi = 0; mi < 4; mi++)
            arow_off[mi] = (uint32_t)(mrow + mi * 16 + (lane & 15)) * 128 + ((lane >> 4) << 4);
#pragma unroll
        for (int p = 0; p < 4; p++)
            brow_off[p] = (uint32_t)(ncolw + p * 16 + (lane & 7) + ((lane >> 4) << 3)) * 128
                          + (((lane >> 3) & 1) << 4);

        int s = 0;
        for (int c = 0; c < NCHUNK; c++) {
            uint32_t base = ab + s * ST_SZ;
            NBAR_SYNC(1 + s);
#pragma unroll
            for (int j = 0; j < 4; j++) {
                uint32_t fa0[4][4], fa1[4][4], fb0[4][4], fb1[4][4];
#pragma unroll
                for (int mi = 0; mi < 4; mi++) {
                    uint32_t off = sw128(arow_off[mi] + j * 32);
                    ldsm4(base + OA0 + off, fa0[mi]);
                    ldsm4(base + OA1 + off, fa1[mi]);
                }
#pragma unroll
                for (int p = 0; p < 4; p++) {
                    uint32_t off = sw128(brow_off[p] + j * 32);
                    ldsm4(base + OB0 + off, fb0[p]);
                    ldsm4(base + OB1 + off, fb1[p]);
                }
#pragma unroll
                for (int mi = 0; mi < 4; mi++)
#pragma unroll
                    for (int p = 0; p < 4; p++)
#pragma unroll
                        for (int hh = 0; hh < 2; hh++)
                            mma16816(acc[mi][2 * p + hh], fa0[mi], &fb0[p][2 * hh]);
#pragma unroll
                for (int mi = 0; mi < 4; mi++)
#pragma unroll
                    for (int p = 0; p < 4; p++)
#pragma unroll
                        for (int hh = 0; hh < 2; hh++)
                            mma16816(acc[mi][2 * p + hh], fa1[mi], &fb0[p][2 * hh]);
#pragma unroll
                for (int mi = 0; mi < 4; mi++)
#pragma unroll
                    for (int p = 0; p < 4; p++)
#pragma unroll
                        for (int hh = 0; hh < 2; hh++)
                            mma16816(acc[mi][2 * p + hh], fa0[mi], &fb1[p][2 * hh]);
            }
            NBAR_ARRIVE(4 + s);
            s = (s == 2) ? 0 : s + 1;
        }

        // epilogue: +bias, store, and accumulate BN column stats
        int g = lane >> 2, t4 = lane & 3;
#pragma unroll
        for (int tn = 0; tn < 8; tn++) {
            int col = ncolw + tn * 8 + 2 * t4;
            float bx = __ldg(&bias[col]);
            float by = __ldg(&bias[col + 1]);
            float sx = 0.f, sy = 0.f, qx = 0.f, qy = 0.f;
#pragma unroll
            for (int mi = 0; mi < 4; mi++) {
                int row0 = bm + mrow + mi * 16 + g;
                float o0 = acc[mi][tn][0] + bx;
                float o1 = acc[mi][tn][1] + by;
                float o2 = acc[mi][tn][2] + bx;
                float o3 = acc[mi][tn][3] + by;
                *(float2*)&g_embed[(size_t)row0 * Ee + col] = make_float2(o0, o1);
                *(float2*)&g_embed[(size_t)(row0 + 8) * Ee + col] = make_float2(o2, o3);
                sx += o0 + o2; sy += o1 + o3;
                qx += o0 * o0 + o2 * o2; qy += o1 * o1 + o3 * o3;
            }
#pragma unroll
            for (int msk = 4; msk < 32; msk <<= 1) {
                sx += __shfl_xor_sync(0xffffffffu, sx, msk);
                sy += __shfl_xor_sync(0xffffffffu, sy, msk);
                qx += __shfl_xor_sync(0xffffffffu, qx, msk);
                qy += __shfl_xor_sync(0xffffffffu, qy, msk);
            }
            if ((lane >> 2) == 0) {
                bn_s[(wid * 8 + tn) * 8 + 2 * t4] = sx;
                bn_s[(wid * 8 + tn) * 8 + 2 * t4 + 1] = sy;
                bn_q[(wid * 8 + tn) * 8 + 2 * t4] = qx;
                bn_q[(wid * 8 + tn) * 8 + 2 * t4 + 1] = qy;
            }
        }
    }
    __syncthreads();
    if (tid < 128) {
        int e = tid;
        int tn = (e & 63) >> 3, k = e & 7;
        int w0 = (e >> 6);
        float s = bn_s[((w0)*8 + tn) * 8 + k] + bn_s[((w0 + 2) * 8 + tn) * 8 + k];
        float q = bn_q[((w0)*8 + tn) * 8 + k] + bn_q[((w0 + 2) * 8 + tn) * 8 + k];
        g_psum[blockIdx.x * 128 + e] = s;
        g_psumsq[blockIdx.x * 128 + e] = q;
    }
}

// ---------------- K4: banded sim + softmax (BN finalize + apply folded) ----
__global__ void k_attn(const float* __restrict__ gamma, const float* __restrict__ beta,
                       float* __restrict__ out_attn) {
    __shared__ float s_et[38 * 129];
    __shared__ float s_ex[8 * 128];
    __shared__ float s_band[8][32];
    __shared__ float s_sc[256], s_sh[256];
    int i0 = blockIdx.x * 8;
    int b = blockIdx.y;
    int jmin = max(0, i0 - HALF_WIN);
    int jmax = min(Nn - 1, i0 + 7 + HALF_WIN);
    int nj = jmax - jmin + 1;
    int tid = threadIdx.x;

    {
        int half = tid >> 7;
        int e = tid & 127;
        float s = 0.f, sq = 0.f;
#pragma unroll 8
        for (int c = 0; c < 64; c++) {
            s += g_psum[(half * 64 + c) * Ee + e];
            sq += g_psumsq[(half * 64 + c) * Ee + e];
        }
        float mean = s / 8192.f;
        float var = sq / 8192.f - mean * mean;
        float rstd = rsqrtf(var + 1e-5f);
        float sc = rstd * __ldg(&gamma[e]);
        s_sc[tid] = sc;
        s_sh[tid] = __ldg(&beta[e]) - mean * sc;
    }
    __syncthreads();

    for (int p = tid; p < nj * 128; p += 256) {
        int jr = p >> 7, k = p & 127;
        float v = g_embed[(size_t)(8192 + b * Nn + jmin + jr) * Ee + k] * s_sc[128 + k] + s_sh[128 + k];
        s_et[jr * 129 + k] = (v >= 0.f) ? v : 0.1f * v;
    }
    for (int p = tid; p < 8 * 128; p += 256) {
        int r = p >> 7, k = p & 127;
        float v = g_embed[(size_t)(b * Nn + i0 + r) * Ee + k] * s_sc[k] + s_sh[k];
        s_ex[r * 128 + k] = (v >= 0.f) ? v : 0.1f * v;
    }
    __syncthreads();

    int w = tid >> 5, lane = tid & 31;
    int i = i0 + w;
    int j0 = max(0, i - HALF_WIN);
    int j1 = min(Nn - 1, i + HALF_WIN);
    int width = j1 - j0 + 1;

    float sim = -1e30f;
    if (lane < width) {
        int jr = j0 + lane - jmin;
        const float* ex = &s_ex[w * 128];
        const float* et = &s_et[jr * 129];
        float a0 = 0.f, a1 = 0.f, a2 = 0.f, a3 = 0.f;
#pragma unroll
        for (int k = 0; k < 128; k += 4) {
            a0 += ex[k] * et[k];
            a1 += ex[k + 1] * et[k + 1];
            a2 += ex[k + 2] * et[k + 2];
            a3 += ex[k + 3] * et[k + 3];
        }
        sim = (a0 + a1) + (a2 + a3);
    }
    float mx = sim;
#pragma unroll
    for (int o = 16; o; o >>= 1) mx = fmaxf(mx, __shfl_xor_sync(0xffffffffu, mx, o));
    float ev = (lane < width) ? expf(sim - mx) : 0.f;
    float sum = ev;
#pragma unroll
    for (int o = 16; o; o >>= 1) sum += __shfl_xor_sync(0xffffffffu, sum, o);
    float a = ev / sum;
    s_band[w][lane] = (lane < width) ? a : 0.f;
    if (lane < width) g_attn_band[(b * Nn + i) * 32 + lane] = a;
    __syncwarp();

    float* rowp = out_attn + ((size_t)(b * Nn + i)) * Nn;
#pragma unroll
    for (int t = 0; t < 16; t++) {
        int j4 = (t * 32 + lane) * 4;
        float4 o = make_float4(0.f, 0.f, 0.f, 0.f);
        if (j4 + 3 >= j0 && j4 <= j1) {
#pragma unroll
            for (int q = 0; q < 4; q++) {
                int j = j4 + q;
                if (j >= j0 && j <= j1) ((float*)&o)[q] = s_band[w][j - j0];
            }
        }
        *(float4*)&rowp[j4] = o;
    }
}

// ---------------- K5: banded attn @ mem via fp16 HMMA, 64-row tiles --------
#define MW_A0 0
#define MW_A1 13312
#define MW_M  26624
#define MW_SMEM (26624 + 50688 + 256)

__global__ void __launch_bounds__(256, 2)
k_memw(const float* __restrict__ sig, const float* __restrict__ mem,
       float* __restrict__ out_mem) {
    extern __shared__ char smw[];
    uint32_t mwb = smem_u32(smw);
    int i0 = blockIdx.x * 64;
    int fc = blockIdx.y * 256;
    int b = blockIdx.z;
    int tid = threadIdx.x;
    int jmin = max(0, i0 - HALF_WIN);
    int jmax = min(Nn - 1, i0 + 63 + HALF_WIN);
    int nj = jmax - jmin + 1;     // <= 94

    __half* s_a0 = (__half*)(smw + MW_A0);
    __half* s_a1 = (__half*)(smw + MW_A1);
    __half* s_m  = (__half*)(smw + MW_M);

    for (int p = tid; p < 6656; p += 256) ((uint32_t*)smw)[p] = 0u;
    __syncthreads();

    for (int q = tid; q < 64 * 32; q += 256) {
        int r = q >> 5, l = q & 31;
        int i = i0 + r;
        int j0 = max(0, i - HALF_WIN);
        int j1 = min(Nn - 1, i + HALF_WIN);
        if (l <= j1 - j0) {
            float a = g_attn_band[(b * Nn + i) * 32 + l];
            __half a0 = __float2half_rn(a);
            float res = a - __half2float(a0);
            int col = (j0 - jmin) + l;
            s_a0[r * 104 + col] = a0;
            s_a1[r * 104 + col] = __float2half_rn(res);
        }
    }
    for (int p = tid; p < 96 * 64; p += 256) {
        int row = p >> 6, f4 = (p & 63) * 4;
        __half2 h0, h1;
        if (row < nj) {
            float4 v = *(const float4*)&mem[(size_t)(b * Nn + jmin + row) * Kk + fc + f4];
            h0 = __floats2half2_rn(v.x, v.y);
            h1 = __floats2half2_rn(v.z, v.w);
        } else {
            h0 = __floats2half2_rn(0.f, 0.f);
            h1 = h0;
        }
        *(__half2*)&s_m[row * 264 + f4] = h0;
        *(__half2*)&s_m[row * 264 + f4 + 2] = h1;
    }
    __syncthreads();

    int wid = tid >> 5, lane = tid & 31;
    uint32_t a0b = mwb + MW_A0;
    uint32_t a1b = mwb + MW_A1;
    uint32_t mb = mwb + MW_M;

    float acc[4][4][4];
#pragma unroll
    for (int mi = 0; mi < 4; mi++)
#pragma unroll
        for (int t = 0; t < 4; t++)
#pragma unroll
            for (int c = 0; c < 4; c++) acc[mi][t][c] = 0.f;

#pragma unroll
    for (int ks = 0; ks < 6; ks++) {
        uint32_t fa0[4][4], fa1[4][4];
#pragma unroll
        for (int mi = 0; mi < 4; mi++) {
            uint32_t row = mi * 16 + (lane & 15);
            uint32_t col = ks * 16 + ((lane >> 4) << 3);
            ldsm4(a0b + (row * 104 + col) * 2, fa0[mi]);
            ldsm4(a1b + (row * 104 + col) * 2, fa1[mi]);
        }
#pragma unroll
        for (int t = 0; t < 4; t++) {
            uint32_t ncol = (wid * 4 + t) * 8;
            uint32_t krow = ks * 16 + (lane & 15);
            uint32_t fb[2];
            ldsm2t(mb + (krow * 264 + ncol) * 2, fb);
#pragma unroll
            for (int mi = 0; mi < 4; mi++) {
                mma16816h(acc[mi][t], fa0[mi], fb);
                mma16816h(acc[mi][t], fa1[mi], fb);
            }
        }
    }

    int g = lane >> 2, t4 = lane & 3;
#pragma unroll
    for (int mi = 0; mi < 4; mi++) {
#pragma unroll
        for (int t = 0; t < 4; t++) {
            int col = wid * 32 + t * 8 + 2 * t4;
            int row0 = i0 + mi * 16 + g;
            size_t base0 = (size_t)(b * Nn + row0) * Kk + fc + col;
            size_t base1 = (size_t)(b * Nn + row0 + 8) * Kk + fc + col;
            float2 sg0 = *(const float2*)&sig[base0];
            float2 sg1 = *(const float2*)&sig[base1];
            float2 o0 = make_float2(0.5f * sg0.x + 0.5f * acc[mi][t][0],
                                    0.5f * sg0.y + 0.5f * acc[mi][t][1]);
            float2 o1 = make_float2(0.5f * sg1.x + 0.5f * acc[mi][t][2],
                                    0.5f * sg1.y + 0.5f * acc[mi][t][3]);
            *(float2*)&out_mem[base0] = o0;
            *(float2*)&out_mem[base1] = o1;
        }
    }
}

// ---------------- launch ----------------
extern "C" void kernel_launch(void* const* d_in, const int* in_sizes, int n_in,
                              void* d_out, int out_size) {
    const float* sig   = (const float*)d_in[0];
    const float* mem   = (const float*)d_in[1];
    const float* w     = (const float*)d_in[2];
    const float* bias  = (const float*)d_in[3];
    const float* gamma = (const float*)d_in[4];
    const float* beta  = (const float*)d_in[5];
    float* out_mem  = (float*)d_out;
    float* out_attn = (float*)d_out + (size_t)Bsz * Nn * Kk;

    static bool attr_done = false;
    if (!attr_done) {
        cudaFuncSetAttribute(k_gemm, cudaFuncAttributeMaxDynamicSharedMemorySize, GEMM_SMEM);
        cudaFuncSetAttribute(k_memw, cudaFuncAttributeMaxDynamicSharedMemorySize, MW_SMEM);
        attr_done = true;
    }

    k_wsplit<<<192, 256>>>(w);                               // launch 0
    k_gemm<<<Mm / 128, 256, GEMM_SMEM>>>(sig, mem, bias);    // launch 1
    k_attn<<<dim3(Nn / 8, Bsz), 256>>>(gamma, beta, out_attn); // launch 2
    k_memw<<<dim3(Nn / 64, 12, Bsz), 256, MW_SMEM>>>(sig, mem, out_mem); // launch 3 -> ncu
}

// round 12
// speedup vs baseline: 1.6599x; 1.0152x over previous
#include <cuda_runtime.h>
#include <cuda_fp16.h>
#include <math.h>
#include <stdint.h>

#define Bsz 4
#define Nn 2048
#define Ee 128
#define Kk 3072            // C*P
#define Mm 16384           // 2*B*N rows (sig half then mem half)
#define HALF_WIN 15
#define NCHUNK 48          // 3072 / 64

// ---------------- scratch ----------------
__device__ float g_embed[Mm * Ee];           // pre-BN y = conv(x)+bias
__device__ float g_psum[128 * Ee];           // per-GEMM-CTA column sums
__device__ float g_psumsq[128 * Ee];
__device__ float g_attn_band[Bsz * Nn * 32];
__device__ uint4 g_w0u[49152];               // W main bf16, CHUNK-major [48][128 rows][8 uint4]
__device__ uint4 g_w1u[49152];               // W residual bf16, same layout

// ---------------- helpers ----------------
__device__ __forceinline__ uint32_t smem_u32(const void* p) {
    uint32_t a;
    asm("{ .reg .u64 t; cvta.to.shared.u64 t, %1; cvt.u32.u64 %0, t; }" : "=r"(a) : "l"(p));
    return a;
}
__device__ __forceinline__ void ldsm4(uint32_t addr, uint32_t* r) {
    asm volatile("ldmatrix.sync.aligned.m8n8.x4.shared.b16 {%0,%1,%2,%3}, [%4];"
                 : "=r"(r[0]), "=r"(r[1]), "=r"(r[2]), "=r"(r[3]) : "r"(addr));
}
__device__ __forceinline__ void ldsm2t(uint32_t addr, uint32_t* r) {
    asm volatile("ldmatrix.sync.aligned.m8n8.x2.trans.shared.b16 {%0,%1}, [%2];"
                 : "=r"(r[0]), "=r"(r[1]) : "r"(addr));
}
__device__ __forceinline__ void mma16816(float* c, const uint32_t* a, const uint32_t* b) {
    asm volatile(
        "mma.sync.aligned.m16n8k16.row.col.f32.bf16.bf16.f32 "
        "{%0,%1,%2,%3}, {%4,%5,%6,%7}, {%8,%9}, {%0,%1,%2,%3};"
        : "+f"(c[0]), "+f"(c[1]), "+f"(c[2]), "+f"(c[3])
        : "r"(a[0]), "r"(a[1]), "r"(a[2]), "r"(a[3]), "r"(b[0]), "r"(b[1]));
}
__device__ __forceinline__ void mma16816h(float* c, const uint32_t* a, const uint32_t* b) {
    asm volatile(
        "mma.sync.aligned.m16n8k16.row.col.f32.f16.f16.f32 "
        "{%0,%1,%2,%3}, {%4,%5,%6,%7}, {%8,%9}, {%0,%1,%2,%3};"
        : "+f"(c[0]), "+f"(c[1]), "+f"(c[2]), "+f"(c[3])
        : "r"(a[0]), "r"(a[1]), "r"(a[2]), "r"(a[3]), "r"(b[0]), "r"(b[1]));
}
#define CP_ASYNC16(dst, src) \
    asm volatile("cp.async.ca.shared.global [%0], [%1], 16;" :: "r"(dst), "l"(src) : "memory")
#define CP_COMMIT  asm volatile("cp.async.commit_group;" ::: "memory")
#define CP_WAIT0   asm volatile("cp.async.wait_group 0;" ::: "memory")
#define NBAR_SYNC(id)   asm volatile("bar.sync %0, 256;" :: "r"(id) : "memory")
#define NBAR_ARRIVE(id) asm volatile("bar.arrive %0, 256;" :: "r"(id) : "memory")

__device__ __forceinline__ uint32_t sw128(uint32_t o) { return o ^ ((o >> 3) & 0x70); }

__device__ __forceinline__ void split4(float4 v, uint32_t& m0, uint32_t& m1,
                                       uint32_t& r0, uint32_t& r1) {
    asm("cvt.rn.bf16x2.f32 %0, %1, %2;" : "=r"(m0) : "f"(v.y), "f"(v.x));
    asm("cvt.rn.bf16x2.f32 %0, %1, %2;" : "=r"(m1) : "f"(v.w), "f"(v.z));
    float e0 = v.x - __uint_as_float(m0 << 16);
    float e1 = v.y - __uint_as_float(m0 & 0xffff0000u);
    float e2 = v.z - __uint_as_float(m1 << 16);
    float e3 = v.w - __uint_as_float(m1 & 0xffff0000u);
    asm("cvt.rn.bf16x2.f32 %0, %1, %2;" : "=r"(r0) : "f"(e1), "f"(e0));
    asm("cvt.rn.bf16x2.f32 %0, %1, %2;" : "=r"(r1) : "f"(e3), "f"(e2));
}

// ---------------- K0: pre-split W into bf16 main + residual (chunk-major) ----
__global__ void k_wsplit(const float* __restrict__ w) {
    int t = blockIdx.x * blockDim.x + threadIdx.x;
    int row = t / 384;
    int kq = t - row * 384;
    int chunk = kq >> 3;
    int piece = kq & 7;
    int out = chunk * 1024 + row * 8 + piece;
    const float* src = w + (size_t)row * Kk + kq * 8;
    float4 u = *(const float4*)src;
    float4 v = *(const float4*)(src + 4);
    uint32_t m0, m1, m2, m3, r0, r1, r2, r3;
    split4(u, m0, m1, r0, r1);
    split4(v, m2, m3, r2, r3);
    g_w0u[out] = make_uint4(m0, m1, m2, m3);
    g_w1u[out] = make_uint4(r0, r1, r2, r3);
}

// ---------------- K1: warp-specialized HMMA GEMM + fused BN stats -----------
#define ST_SZ 65536
#define OA0 0
#define OA1 16384
#define OB0 32768
#define OB1 49152
#define GEMM_SMEM (1024 + 3 * ST_SZ + 2048)

__global__ void __launch_bounds__(256, 1)
k_gemm(const float* __restrict__ sig, const float* __restrict__ mem,
       const float* __restrict__ bias) {
    extern __shared__ char smraw[];
    uint32_t sb = smem_u32(smraw);
    uint32_t ab = (sb + 1023) & ~1023u;
    char* sm = smraw + (ab - sb);

    int tid = threadIdx.x;
    int wid = tid >> 5, lane = tid & 31;

    int bm = blockIdx.x * 128;
    const float* X = (bm < 8192) ? sig : mem;
    int rb = (bm < 8192) ? bm : bm - 8192;

    float* bn_s = (float*)(sm + 3 * ST_SZ);
    float* bn_q = bn_s + 256;

    if (wid >= 4) {
        // ================= PRODUCER =================
        int pt = tid - 128;
        int prow = pt >> 4;
        int pf4 = pt & 15;
        const float* Xb = X + (size_t)rb * Kk + pf4 * 4;

        int s = 0;
        for (int c = 0; c < NCHUNK; c++) {
            uint32_t base = ab + s * ST_SZ;
            char* smA0 = sm + s * ST_SZ + OA0;
            char* smA1 = sm + s * ST_SZ + OA1;
            if (c >= 3) NBAR_SYNC(4 + s);

            const uint4* w0c = g_w0u + c * 1024;
            const uint4* w1c = g_w1u + c * 1024;
#pragma unroll
            for (int q = 0; q < 8; q++) {
                int idx = q * 128 + pt;
                uint32_t off = sw128((uint32_t)(idx >> 3) * 128 + (idx & 7) * 16);
                CP_ASYNC16(base + OB0 + off, w0c + idx);
                CP_ASYNC16(base + OB1 + off, w1c + idx);
            }
            CP_COMMIT;

            const float* src = Xb + c * 64;
#pragma unroll
            for (int batch = 0; batch < 2; batch++) {
                float4 v[8];
#pragma unroll
                for (int i = 0; i < 8; i++) {
                    int r = (batch * 8 + i) * 8 + prow;
                    v[i] = *(const float4*)(src + (size_t)r * Kk);
                }
#pragma unroll
                for (int i = 0; i < 8; i++) {
                    int r = (batch * 8 + i) * 8 + prow;
                    uint32_t o = sw128((uint32_t)r * 128 + pf4 * 8);
                    uint32_t m0, m1, r0, r1;
                    split4(v[i], m0, m1, r0, r1);
                    *(uint2*)(smA0 + o) = make_uint2(m0, m1);
                    *(uint2*)(smA1 + o) = make_uint2(r0, r1);
                }
            }
            CP_WAIT0;
            asm volatile("membar.cta;" ::: "memory");
            NBAR_ARRIVE(1 + s);
            s = (s == 2) ? 0 : s + 1;
        }
    } else {
        // ================= CONSUMER =================
        int mrow = (wid >> 1) * 64;
        int ncolw = (wid & 1) * 64;

        float acc[4][8][4];
#pragma unroll
        for (int a = 0; a < 4; a++)
#pragma unroll
            for (int b = 0; b < 8; b++)
#pragma unroll
                for (int c = 0; c < 4; c++) acc[a][b][c] = 0.f;

        uint32_t arow_off[4], brow_off[4];
#pragma unroll
        for (int mi = 0; mi < 4; mi++)
            arow_off[mi] = (uint32_t)(mrow + mi * 16 + (lane & 15)) * 128 + ((lane >> 4) << 4);
#pragma unroll
        for (int p = 0; p < 4; p++)
            brow_off[p] = (uint32_t)(ncolw + p * 16 + (lane & 7) + ((lane >> 4) << 3)) * 128
                          + (((lane >> 3) & 1) << 4);

        int s = 0;
        for (int c = 0; c < NCHUNK; c++) {
            uint32_t base = ab + s * ST_SZ;
            NBAR_SYNC(1 + s);
#pragma unroll
            for (int j = 0; j < 4; j++) {
                uint32_t fa0[4][4], fa1[4][4], fb0[4][4], fb1[4][4];
#pragma unroll
                for (int mi = 0; mi < 4; mi++) {
                    uint32_t off = sw128(arow_off[mi] + j * 32);
                    ldsm4(base + OA0 + off, fa0[mi]);
                    ldsm4(base + OA1 + off, fa1[mi]);
                }
#pragma unroll
                for (int p = 0; p < 4; p++) {
                    uint32_t off = sw128(brow_off[p] + j * 32);
                    ldsm4(base + OB0 + off, fb0[p]);
                    ldsm4(base + OB1 + off, fb1[p]);
                }
#pragma unroll
                for (int mi = 0; mi < 4; mi++)
#pragma unroll
                    for (int p = 0; p < 4; p++)
#pragma unroll
                        for (int hh = 0; hh < 2; hh++)
                            mma16816(acc[mi][2 * p + hh], fa0[mi], &fb0[p][2 * hh]);
#pragma unroll
                for (int mi = 0; mi < 4; mi++)
#pragma unroll
                    for (int p = 0; p < 4; p++)
#pragma unroll
                        for (int hh = 0; hh < 2; hh++)
                            mma16816(acc[mi][2 * p + hh], fa1[mi], &fb0[p][2 * hh]);
#pragma unroll
                for (int mi = 0; mi < 4; mi++)
#pragma unroll
                    for (int p = 0; p < 4; p++)
#pragma unroll
                        for (int hh = 0; hh < 2; hh++)
                            mma16816(acc[mi][2 * p + hh], fa0[mi], &fb1[p][2 * hh]);
            }
            NBAR_ARRIVE(4 + s);
            s = (s == 2) ? 0 : s + 1;
        }

        int g = lane >> 2, t4 = lane & 3;
#pragma unroll
        for (int tn = 0; tn < 8; tn++) {
            int col = ncolw + tn * 8 + 2 * t4;
            float bx = __ldg(&bias[col]);
            float by = __ldg(&bias[col + 1]);
            float sx = 0.f, sy = 0.f, qx = 0.f, qy = 0.f;
#pragma unroll
            for (int mi = 0; mi < 4; mi++) {
                int row0 = bm + mrow + mi * 16 + g;
                float o0 = acc[mi][tn][0] + bx;
                float o1 = acc[mi][tn][1] + by;
                float o2 = acc[mi][tn][2] + bx;
                float o3 = acc[mi][tn][3] + by;
                *(float2*)&g_embed[(size_t)row0 * Ee + col] = make_float2(o0, o1);
                *(float2*)&g_embed[(size_t)(row0 + 8) * Ee + col] = make_float2(o2, o3);
                sx += o0 + o2; sy += o1 + o3;
                qx += o0 * o0 + o2 * o2; qy += o1 * o1 + o3 * o3;
            }
#pragma unroll
            for (int msk = 4; msk < 32; msk <<= 1) {
                sx += __shfl_xor_sync(0xffffffffu, sx, msk);
                sy += __shfl_xor_sync(0xffffffffu, sy, msk);
                qx += __shfl_xor_sync(0xffffffffu, qx, msk);
                qy += __shfl_xor_sync(0xffffffffu, qy, msk);
            }
            if ((lane >> 2) == 0) {
                bn_s[(wid * 8 + tn) * 8 + 2 * t4] = sx;
                bn_s[(wid * 8 + tn) * 8 + 2 * t4 + 1] = sy;
                bn_q[(wid * 8 + tn) * 8 + 2 * t4] = qx;
                bn_q[(wid * 8 + tn) * 8 + 2 * t4 + 1] = qy;
            }
        }
    }
    __syncthreads();
    if (tid < 128) {
        int e = tid;
        int tn = (e & 63) >> 3, k = e & 7;
        int w0 = (e >> 6);
        float s = bn_s[((w0)*8 + tn) * 8 + k] + bn_s[((w0 + 2) * 8 + tn) * 8 + k];
        float q = bn_q[((w0)*8 + tn) * 8 + k] + bn_q[((w0 + 2) * 8 + tn) * 8 + k];
        g_psum[blockIdx.x * 128 + e] = s;
        g_psumsq[blockIdx.x * 128 + e] = q;
    }
}

// ---------------- K4: banded sim + softmax (BN finalize + apply folded) ----
__global__ void k_attn(const float* __restrict__ gamma, const float* __restrict__ beta,
                       float* __restrict__ out_attn) {
    __shared__ float s_et[38 * 129];
    __shared__ float s_ex[8 * 128];
    __shared__ float s_band[8][32];
    __shared__ float s_sc[256], s_sh[256];
    int i0 = blockIdx.x * 8;
    int b = blockIdx.y;
    int jmin = max(0, i0 - HALF_WIN);
    int jmax = min(Nn - 1, i0 + 7 + HALF_WIN);
    int nj = jmax - jmin + 1;
    int tid = threadIdx.x;

    {
        int half = tid >> 7;
        int e = tid & 127;
        float s = 0.f, sq = 0.f;
#pragma unroll 8
        for (int c = 0; c < 64; c++) {
            s += g_psum[(half * 64 + c) * Ee + e];
            sq += g_psumsq[(half * 64 + c) * Ee + e];
        }
        float mean = s / 8192.f;
        float var = sq / 8192.f - mean * mean;
        float rstd = rsqrtf(var + 1e-5f);
        float sc = rstd * __ldg(&gamma[e]);
        s_sc[tid] = sc;
        s_sh[tid] = __ldg(&beta[e]) - mean * sc;
    }
    __syncthreads();

    for (int p = tid; p < nj * 128; p += 256) {
        int jr = p >> 7, k = p & 127;
        float v = g_embed[(size_t)(8192 + b * Nn + jmin + jr) * Ee + k] * s_sc[128 + k] + s_sh[128 + k];
        s_et[jr * 129 + k] = (v >= 0.f) ? v : 0.1f * v;
    }
    for (int p = tid; p < 8 * 128; p += 256) {
        int r = p >> 7, k = p & 127;
        float v = g_embed[(size_t)(b * Nn + i0 + r) * Ee + k] * s_sc[k] + s_sh[k];
        s_ex[r * 128 + k] = (v >= 0.f) ? v : 0.1f * v;
    }
    __syncthreads();

    int w = tid >> 5, lane = tid & 31;
    int i = i0 + w;
    int j0 = max(0, i - HALF_WIN);
    int j1 = min(Nn - 1, i + HALF_WIN);
    int width = j1 - j0 + 1;

    float sim = -1e30f;
    if (lane < width) {
        int jr = j0 + lane - jmin;
        const float* ex = &s_ex[w * 128];
        const float* et = &s_et[jr * 129];
        float a0 = 0.f, a1 = 0.f, a2 = 0.f, a3 = 0.f;
#pragma unroll
        for (int k = 0; k < 128; k += 4) {
            a0 += ex[k] * et[k];
            a1 += ex[k + 1] * et[k + 1];
            a2 += ex[k + 2] * et[k + 2];
            a3 += ex[k + 3] * et[k + 3];
        }
        sim = (a0 + a1) + (a2 + a3);
    }
    float mx = sim;
#pragma unroll
    for (int o = 16; o; o >>= 1) mx = fmaxf(mx, __shfl_xor_sync(0xffffffffu, mx, o));
    float ev = (lane < width) ? expf(sim - mx) : 0.f;
    float sum = ev;
#pragma unroll
    for (int o = 16; o; o >>= 1) sum += __shfl_xor_sync(0xffffffffu, sum, o);
    float a = ev / sum;
    s_band[w][lane] = (lane < width) ? a : 0.f;
    if (lane < width) g_attn_band[(b * Nn + i) * 32 + lane] = a;
    __syncwarp();

    float* rowp = out_attn + ((size_t)(b * Nn + i)) * Nn;
#pragma unroll
    for (int t = 0; t < 16; t++) {
        int j4 = (t * 32 + lane) * 4;
        float4 o = make_float4(0.f, 0.f, 0.f, 0.f);
        if (j4 + 3 >= j0 && j4 <= j1) {
#pragma unroll
            for (int q = 0; q < 4; q++) {
                int j = j4 + q;
                if (j >= j0 && j <= j1) ((float*)&o)[q] = s_band[w][j - j0];
            }
        }
        *(float4*)&rowp[j4] = o;
    }
}

// ---------------- K5: banded attn @ mem via fp16 HMMA, diagonal K-windows ---
// Virtual base jv = i0 - 15 (un-clamped). Group mi window = k-rows [16mi,16mi+48)
// relative to jv; mem rows outside [0,Nn) are zero-filled.
#define MW_A0 0
#define MW_A1 7168
#define MW_M  14336
#define MW_SMEM (14336 + 50688 + 256)

__global__ void __launch_bounds__(256, 2)
k_memw(const float* __restrict__ sig, const float* __restrict__ mem,
       float* __restrict__ out_mem) {
    extern __shared__ char smw[];
    uint32_t mwb = smem_u32(smw);
    int i0 = blockIdx.x * 64;
    int fc = blockIdx.y * 256;
    int b = blockIdx.z;
    int tid = threadIdx.x;
    int jv = i0 - HALF_WIN;       // virtual (signed) base; may be -15

    __half* s_a0 = (__half*)(smw + MW_A0);   // [64][56], window per 16-row group
    __half* s_a1 = (__half*)(smw + MW_A1);
    __half* s_m  = (__half*)(smw + MW_M);    // [96][264]

    for (int p = tid; p < 3584; p += 256) ((uint32_t*)smw)[p] = 0u;
    __syncthreads();

    // fill attn band (fp16 split) into per-group windows relative to jv
    for (int q = tid; q < 64 * 32; q += 256) {
        int r = q >> 5, l = q & 31;
        int i = i0 + r;
        int j0 = max(0, i - HALF_WIN);
        int j1 = min(Nn - 1, i + HALF_WIN);
        if (l <= j1 - j0) {
            float a = g_attn_band[(b * Nn + i) * 32 + l];
            __half a0 = __float2half_rn(a);
            float res = a - __half2float(a0);
            int col = (j0 + l) - jv - (r & ~15);   // in [r&15, 45]
            s_a0[r * 56 + col] = a0;
            s_a1[r * 56 + col] = __float2half_rn(res);
        }
    }
    // fill mem tile [96][264]: row -> absolute ja = jv + row, zero outside [0,Nn)
    for (int p = tid; p < 96 * 64; p += 256) {
        int row = p >> 6, f4 = (p & 63) * 4;
        int ja = jv + row;
        __half2 h0, h1;
        if (ja >= 0 && ja < Nn) {
            float4 v = *(const float4*)&mem[(size_t)(b * Nn + ja) * Kk + fc + f4];
            h0 = __floats2half2_rn(v.x, v.y);
            h1 = __floats2half2_rn(v.z, v.w);
        } else {
            h0 = __floats2half2_rn(0.f, 0.f);
            h1 = h0;
        }
        *(__half2*)&s_m[row * 264 + f4] = h0;
        *(__half2*)&s_m[row * 264 + f4 + 2] = h1;
    }
    __syncthreads();

    int wid = tid >> 5, lane = tid & 31;
    uint32_t a0b = mwb + MW_A0;
    uint32_t a1b = mwb + MW_A1;
    uint32_t mb = mwb + MW_M;

    float acc[4][4][4];   // [mi][t][4]
#pragma unroll
    for (int mi = 0; mi < 4; mi++)
#pragma unroll
        for (int t = 0; t < 4; t++)
#pragma unroll
            for (int c = 0; c < 4; c++) acc[mi][t][c] = 0.f;

    // loop over absolute k-steps; share B fragment across the <=3 groups using it
#pragma unroll
    for (int q = 0; q < 6; q++) {
        uint32_t fb[4][2];
        uint32_t krow = q * 16 + (lane & 15);
#pragma unroll
        for (int t = 0; t < 4; t++) {
            uint32_t ncol = (wid * 4 + t) * 8;
            ldsm2t(mb + (krow * 264 + ncol) * 2, fb[t]);
        }
        int mlo = (q - 2 > 0) ? q - 2 : 0;
        int mhi = (q < 3) ? q : 3;
#pragma unroll
        for (int mi = 0; mi < 4; mi++) {
            if (mi < mlo || mi > mhi) continue;
            int ks = q - mi;    // 0..2
            uint32_t row = mi * 16 + (lane & 15);
            uint32_t col = ks * 16 + ((lane >> 4) << 3);
            uint32_t fa0[4], fa1[4];
            ldsm4(a0b + (row * 56 + col) * 2, fa0);
            ldsm4(a1b + (row * 56 + col) * 2, fa1);
#pragma unroll
            for (int t = 0; t < 4; t++) {
                mma16816h(acc[mi][t], fa0, fb[t]);
                mma16816h(acc[mi][t], fa1, fb[t]);
            }
        }
    }

    // blend + store directly from fragments
    int g = lane >> 2, t4 = lane & 3;
#pragma unroll
    for (int mi = 0; mi < 4; mi++) {
#pragma unroll
        for (int t = 0; t < 4; t++) {
            int col = wid * 32 + t * 8 + 2 * t4;
            int row0 = i0 + mi * 16 + g;
            size_t base0 = (size_t)(b * Nn + row0) * Kk + fc + col;
            size_t base1 = (size_t)(b * Nn + row0 + 8) * Kk + fc + col;
            float2 sg0 = *(const float2*)&sig[base0];
            float2 sg1 = *(const float2*)&sig[base1];
            float2 o0 = make_float2(0.5f * sg0.x + 0.5f * acc[mi][t][0],
                                    0.5f * sg0.y + 0.5f * acc[mi][t][1]);
            float2 o1 = make_float2(0.5f * sg1.x + 0.5f * acc[mi][t][2],
                                    0.5f * sg1.y + 0.5f * acc[mi][t][3]);
            *(float2*)&out_mem[base0] = o0;
            *(float2*)&out_mem[base1] = o1;
        }
    }
}

// ---------------- launch ----------------
extern "C" void kernel_launch(void* const* d_in, const int* in_sizes, int n_in,
                              void* d_out, int out_size) {
    const float* sig   = (const float*)d_in[0];
    const float* mem   = (const float*)d_in[1];
    const float* w     = (const float*)d_in[2];
    const float* bias  = (const float*)d_in[3];
    const float* gamma = (const float*)d_in[4];
    const float* beta  = (const float*)d_in[5];
    float* out_mem  = (float*)d_out;
    float* out_attn = (float*)d_out + (size_t)Bsz * Nn * Kk;

    static bool attr_done = false;
    if (!attr_done) {
        cudaFuncSetAttribute(k_gemm, cudaFuncAttributeMaxDynamicSharedMemorySize, GEMM_SMEM);
        cudaFuncSetAttribute(k_memw, cudaFuncAttributeMaxDynamicSharedMemorySize, MW_SMEM);
        attr_done = true;
    }

    k_wsplit<<<192, 256>>>(w);                               // launch 0
    k_gemm<<<Mm / 128, 256, GEMM_SMEM>>>(sig, mem, bias);    // launch 1
    k_attn<<<dim3(Nn / 8, Bsz), 256>>>(gamma, beta, out_attn); // launch 2
    k_memw<<<dim3(Nn / 64, 12, Bsz), 256, MW_SMEM>>>(sig, mem, out_mem); // launch 3 -> ncu
}

// round 13
// speedup vs baseline: 1.8489x; 1.1139x over previous
#include <cuda_runtime.h>
#include <cuda_fp16.h>
#include <math.h>
#include <stdint.h>

#define Bsz 4
#define Nn 2048
#define Ee 128
#define Kk 3072            // C*P
#define Mm 16384           // 2*B*N rows (sig half then mem half)
#define HALF_WIN 15
#define NCHUNK 48          // 3072 / 64

// ---------------- scratch ----------------
__device__ float g_embed[Mm * Ee];           // pre-BN y = conv(x)+bias
__device__ float g_psum[128 * Ee];           // per-GEMM-CTA column sums
__device__ float g_psumsq[128 * Ee];
__device__ float g_attn_band[Bsz * Nn * 32];
__device__ uint4 g_w0u[49152];               // W main bf16, CHUNK-major [48][128 rows][8 uint4]
__device__ uint4 g_w1u[49152];               // W residual bf16, same layout

// ---------------- helpers ----------------
__device__ __forceinline__ uint32_t smem_u32(const void* p) {
    uint32_t a;
    asm("{ .reg .u64 t; cvta.to.shared.u64 t, %1; cvt.u32.u64 %0, t; }" : "=r"(a) : "l"(p));
    return a;
}
__device__ __forceinline__ void ldsm4(uint32_t addr, uint32_t* r) {
    asm volatile("ldmatrix.sync.aligned.m8n8.x4.shared.b16 {%0,%1,%2,%3}, [%4];"
                 : "=r"(r[0]), "=r"(r[1]), "=r"(r[2]), "=r"(r[3]) : "r"(addr));
}
__device__ __forceinline__ void ldsm2t(uint32_t addr, uint32_t* r) {
    asm volatile("ldmatrix.sync.aligned.m8n8.x2.trans.shared.b16 {%0,%1}, [%2];"
                 : "=r"(r[0]), "=r"(r[1]) : "r"(addr));
}
__device__ __forceinline__ void mma16816(float* c, const uint32_t* a, const uint32_t* b) {
    asm volatile(
        "mma.sync.aligned.m16n8k16.row.col.f32.bf16.bf16.f32 "
        "{%0,%1,%2,%3}, {%4,%5,%6,%7}, {%8,%9}, {%0,%1,%2,%3};"
        : "+f"(c[0]), "+f"(c[1]), "+f"(c[2]), "+f"(c[3])
        : "r"(a[0]), "r"(a[1]), "r"(a[2]), "r"(a[3]), "r"(b[0]), "r"(b[1]));
}
__device__ __forceinline__ void mma16816h(float* c, const uint32_t* a, const uint32_t* b) {
    asm volatile(
        "mma.sync.aligned.m16n8k16.row.col.f32.f16.f16.f32 "
        "{%0,%1,%2,%3}, {%4,%5,%6,%7}, {%8,%9}, {%0,%1,%2,%3};"
        : "+f"(c[0]), "+f"(c[1]), "+f"(c[2]), "+f"(c[3])
        : "r"(a[0]), "r"(a[1]), "r"(a[2]), "r"(a[3]), "r"(b[0]), "r"(b[1]));
}
#define CP_ASYNC16(dst, src) \
    asm volatile("cp.async.ca.shared.global [%0], [%1], 16;" :: "r"(dst), "l"(src) : "memory")
#define CP_COMMIT  asm volatile("cp.async.commit_group;" ::: "memory")
#define CP_WAIT0   asm volatile("cp.async.wait_group 0;" ::: "memory")
#define NBAR_SYNC(id)   asm volatile("bar.sync %0, 256;" :: "r"(id) : "memory")
#define NBAR_ARRIVE(id) asm volatile("bar.arrive %0, 256;" :: "r"(id) : "memory")

__device__ __forceinline__ uint32_t sw128(uint32_t o) { return o ^ ((o >> 3) & 0x70); }

__device__ __forceinline__ void split4(float4 v, uint32_t& m0, uint32_t& m1,
                                       uint32_t& r0, uint32_t& r1) {
    asm("cvt.rn.bf16x2.f32 %0, %1, %2;" : "=r"(m0) : "f"(v.y), "f"(v.x));
    asm("cvt.rn.bf16x2.f32 %0, %1, %2;" : "=r"(m1) : "f"(v.w), "f"(v.z));
    float e0 = v.x - __uint_as_float(m0 << 16);
    float e1 = v.y - __uint_as_float(m0 & 0xffff0000u);
    float e2 = v.z - __uint_as_float(m1 << 16);
    float e3 = v.w - __uint_as_float(m1 & 0xffff0000u);
    asm("cvt.rn.bf16x2.f32 %0, %1, %2;" : "=r"(r0) : "f"(e1), "f"(e0));
    asm("cvt.rn.bf16x2.f32 %0, %1, %2;" : "=r"(r1) : "f"(e3), "f"(e2));
}

// ---------------- K0: pre-split W into bf16 main + residual (chunk-major) ----
__global__ void k_wsplit(const float* __restrict__ w) {
    int t = blockIdx.x * blockDim.x + threadIdx.x;
    int row = t / 384;
    int kq = t - row * 384;
    int chunk = kq >> 3;
    int piece = kq & 7;
    int out = chunk * 1024 + row * 8 + piece;
    const float* src = w + (size_t)row * Kk + kq * 8;
    float4 u = *(const float4*)src;
    float4 v = *(const float4*)(src + 4);
    uint32_t m0, m1, m2, m3, r0, r1, r2, r3;
    split4(u, m0, m1, r0, r1);
    split4(v, m2, m3, r2, r3);
    g_w0u[out] = make_uint4(m0, m1, m2, m3);
    g_w1u[out] = make_uint4(r0, r1, r2, r3);
}

// ---------------- K1: warp-specialized HMMA GEMM + fused BN stats -----------
#define ST_SZ 65536
#define OA0 0
#define OA1 16384
#define OB0 32768
#define OB1 49152
#define GEMM_SMEM (1024 + 3 * ST_SZ + 2048)

__global__ void __launch_bounds__(256, 1)
k_gemm(const float* __restrict__ sig, const float* __restrict__ mem,
       const float* __restrict__ bias) {
    extern __shared__ char smraw[];
    uint32_t sb = smem_u32(smraw);
    uint32_t ab = (sb + 1023) & ~1023u;
    char* sm = smraw + (ab - sb);

    int tid = threadIdx.x;
    int wid = tid >> 5, lane = tid & 31;

    int bm = blockIdx.x * 128;
    const float* X = (bm < 8192) ? sig : mem;
    int rb = (bm < 8192) ? bm : bm - 8192;

    float* bn_s = (float*)(sm + 3 * ST_SZ);
    float* bn_q = bn_s + 256;

    if (wid >= 4) {
        // ================= PRODUCER =================
        int pt = tid - 128;
        int prow = pt >> 4;
        int pf4 = pt & 15;
        const float* Xb = X + (size_t)rb * Kk + pf4 * 4;

        int s = 0;
        for (int c = 0; c < NCHUNK; c++) {
            uint32_t base = ab + s * ST_SZ;
            char* smA0 = sm + s * ST_SZ + OA0;
            char* smA1 = sm + s * ST_SZ + OA1;
            if (c >= 3) NBAR_SYNC(4 + s);

            const uint4* w0c = g_w0u + c * 1024;
            const uint4* w1c = g_w1u + c * 1024;
#pragma unroll
            for (int q = 0; q < 8; q++) {
                int idx = q * 128 + pt;
                uint32_t off = sw128((uint32_t)(idx >> 3) * 128 + (idx & 7) * 16);
                CP_ASYNC16(base + OB0 + off, w0c + idx);
                CP_ASYNC16(base + OB1 + off, w1c + idx);
            }
            CP_COMMIT;

            const float* src = Xb + c * 64;
#pragma unroll
            for (int batch = 0; batch < 2; batch++) {
                float4 v[8];
#pragma unroll
                for (int i = 0; i < 8; i++) {
                    int r = (batch * 8 + i) * 8 + prow;
                    v[i] = *(const float4*)(src + (size_t)r * Kk);
                }
#pragma unroll
                for (int i = 0; i < 8; i++) {
                    int r = (batch * 8 + i) * 8 + prow;
                    uint32_t o = sw128((uint32_t)r * 128 + pf4 * 8);
                    uint32_t m0, m1, r0, r1;
                    split4(v[i], m0, m1, r0, r1);
                    *(uint2*)(smA0 + o) = make_uint2(m0, m1);
                    *(uint2*)(smA1 + o) = make_uint2(r0, r1);
                }
            }
            CP_WAIT0;
            asm volatile("membar.cta;" ::: "memory");
            NBAR_ARRIVE(1 + s);
            s = (s == 2) ? 0 : s + 1;
        }
    } else {
        // ================= CONSUMER =================
        int mrow = (wid >> 1) * 64;
        int ncolw = (wid & 1) * 64;

        float acc[4][8][4];
#pragma unroll
        for (int a = 0; a < 4; a++)
#pragma unroll
            for (int b = 0; b < 8; b++)
#pragma unroll
                for (int c = 0; c < 4; c++) acc[a][b][c] = 0.f;

        uint32_t arow_off[4], brow_off[4];
#pragma unroll
        for (int mi = 0; mi < 4; mi++)
            arow_off[mi] = (uint32_t)(mrow + mi * 16 + (lane & 15)) * 128 + ((lane >> 4) << 4);
#pragma unroll
        for (int p = 0; p < 4; p++)
            brow_off[p] = (uint32_t)(ncolw + p * 16 + (lane & 7) + ((lane >> 4) << 3)) * 128
                          + (((lane >> 3) & 1) << 4);

        int s = 0;
        for (int c = 0; c < NCHUNK; c++) {
            uint32_t base = ab + s * ST_SZ;
            NBAR_SYNC(1 + s);
#pragma unroll
            for (int j = 0; j < 4; j++) {
                uint32_t fa0[4][4], fa1[4][4], fb0[4][4], fb1[4][4];
#pragma unroll
                for (int mi = 0; mi < 4; mi++) {
                    uint32_t off = sw128(arow_off[mi] + j * 32);
                    ldsm4(base + OA0 + off, fa0[mi]);
                    ldsm4(base + OA1 + off, fa1[mi]);
                }
#pragma unroll
                for (int p = 0; p < 4; p++) {
                    uint32_t off = sw128(brow_off[p] + j * 32);
                    ldsm4(base + OB0 + off, fb0[p]);
                    ldsm4(base + OB1 + off, fb1[p]);
                }
#pragma unroll
                for (int mi = 0; mi < 4; mi++)
#pragma unroll
                    for (int p = 0; p < 4; p++)
#pragma unroll
                        for (int hh = 0; hh < 2; hh++)
                            mma16816(acc[mi][2 * p + hh], fa0[mi], &fb0[p][2 * hh]);
#pragma unroll
                for (int mi = 0; mi < 4; mi++)
#pragma unroll
                    for (int p = 0; p < 4; p++)
#pragma unroll
                        for (int hh = 0; hh < 2; hh++)
                            mma16816(acc[mi][2 * p + hh], fa1[mi], &fb0[p][2 * hh]);
#pragma unroll
                for (int mi = 0; mi < 4; mi++)
#pragma unroll
                    for (int p = 0; p < 4; p++)
#pragma unroll
                        for (int hh = 0; hh < 2; hh++)
                            mma16816(acc[mi][2 * p + hh], fa0[mi], &fb1[p][2 * hh]);
            }
            NBAR_ARRIVE(4 + s);
            s = (s == 2) ? 0 : s + 1;
        }

        int g = lane >> 2, t4 = lane & 3;
#pragma unroll
        for (int tn = 0; tn < 8; tn++) {
            int col = ncolw + tn * 8 + 2 * t4;
            float bx = __ldg(&bias[col]);
            float by = __ldg(&bias[col + 1]);
            float sx = 0.f, sy = 0.f, qx = 0.f, qy = 0.f;
#pragma unroll
            for (int mi = 0; mi < 4; mi++) {
                int row0 = bm + mrow + mi * 16 + g;
                float o0 = acc[mi][tn][0] + bx;
                float o1 = acc[mi][tn][1] + by;
                float o2 = acc[mi][tn][2] + bx;
                float o3 = acc[mi][tn][3] + by;
                *(float2*)&g_embed[(size_t)row0 * Ee + col] = make_float2(o0, o1);
                *(float2*)&g_embed[(size_t)(row0 + 8) * Ee + col] = make_float2(o2, o3);
                sx += o0 + o2; sy += o1 + o3;
                qx += o0 * o0 + o2 * o2; qy += o1 * o1 + o3 * o3;
            }
#pragma unroll
            for (int msk = 4; msk < 32; msk <<= 1) {
                sx += __shfl_xor_sync(0xffffffffu, sx, msk);
                sy += __shfl_xor_sync(0xffffffffu, sy, msk);
                qx += __shfl_xor_sync(0xffffffffu, qx, msk);
                qy += __shfl_xor_sync(0xffffffffu, qy, msk);
            }
            if ((lane >> 2) == 0) {
                bn_s[(wid * 8 + tn) * 8 + 2 * t4] = sx;
                bn_s[(wid * 8 + tn) * 8 + 2 * t4 + 1] = sy;
                bn_q[(wid * 8 + tn) * 8 + 2 * t4] = qx;
                bn_q[(wid * 8 + tn) * 8 + 2 * t4 + 1] = qy;
            }
        }
    }
    __syncthreads();
    if (tid < 128) {
        int e = tid;
        int tn = (e & 63) >> 3, k = e & 7;
        int w0 = (e >> 6);
        float s = bn_s[((w0)*8 + tn) * 8 + k] + bn_s[((w0 + 2) * 8 + tn) * 8 + k];
        float q = bn_q[((w0)*8 + tn) * 8 + k] + bn_q[((w0 + 2) * 8 + tn) * 8 + k];
        g_psum[blockIdx.x * 128 + e] = s;
        g_psumsq[blockIdx.x * 128 + e] = q;
    }
}

// ---------------- K4: banded sim + softmax (BN finalize + apply folded) ----
__global__ void k_attn(const float* __restrict__ gamma, const float* __restrict__ beta,
                       float* __restrict__ out_attn) {
    __shared__ float s_et[38 * 129];
    __shared__ float s_ex[8 * 128];
    __shared__ float s_band[8][32];
    __shared__ float s_sc[256], s_sh[256];
    int i0 = blockIdx.x * 8;
    int b = blockIdx.y;
    int jmin = max(0, i0 - HALF_WIN);
    int jmax = min(Nn - 1, i0 + 7 + HALF_WIN);
    int nj = jmax - jmin + 1;
    int tid = threadIdx.x;

    {
        int half = tid >> 7;
        int e = tid & 127;
        float s = 0.f, sq = 0.f;
#pragma unroll 8
        for (int c = 0; c < 64; c++) {
            s += g_psum[(half * 64 + c) * Ee + e];
            sq += g_psumsq[(half * 64 + c) * Ee + e];
        }
        float mean = s / 8192.f;
        float var = sq / 8192.f - mean * mean;
        float rstd = rsqrtf(var + 1e-5f);
        float sc = rstd * __ldg(&gamma[e]);
        s_sc[tid] = sc;
        s_sh[tid] = __ldg(&beta[e]) - mean * sc;
    }
    __syncthreads();

    for (int p = tid; p < nj * 128; p += 256) {
        int jr = p >> 7, k = p & 127;
        float v = g_embed[(size_t)(8192 + b * Nn + jmin + jr) * Ee + k] * s_sc[128 + k] + s_sh[128 + k];
        s_et[jr * 129 + k] = (v >= 0.f) ? v : 0.1f * v;
    }
    for (int p = tid; p < 8 * 128; p += 256) {
        int r = p >> 7, k = p & 127;
        float v = g_embed[(size_t)(b * Nn + i0 + r) * Ee + k] * s_sc[k] + s_sh[k];
        s_ex[r * 128 + k] = (v >= 0.f) ? v : 0.1f * v;
    }
    __syncthreads();

    int w = tid >> 5, lane = tid & 31;
    int i = i0 + w;
    int j0 = max(0, i - HALF_WIN);
    int j1 = min(Nn - 1, i + HALF_WIN);
    int width = j1 - j0 + 1;

    float sim = -1e30f;
    if (lane < width) {
        int jr = j0 + lane - jmin;
        const float* ex = &s_ex[w * 128];
        const float* et = &s_et[jr * 129];
        float a0 = 0.f, a1 = 0.f, a2 = 0.f, a3 = 0.f;
#pragma unroll
        for (int k = 0; k < 128; k += 4) {
            a0 += ex[k] * et[k];
            a1 += ex[k + 1] * et[k + 1];
            a2 += ex[k + 2] * et[k + 2];
            a3 += ex[k + 3] * et[k + 3];
        }
        sim = (a0 + a1) + (a2 + a3);
    }
    float mx = sim;
#pragma unroll
    for (int o = 16; o; o >>= 1) mx = fmaxf(mx, __shfl_xor_sync(0xffffffffu, mx, o));
    float ev = (lane < width) ? expf(sim - mx) : 0.f;
    float sum = ev;
#pragma unroll
    for (int o = 16; o; o >>= 1) sum += __shfl_xor_sync(0xffffffffu, sum, o);
    float a = ev / sum;
    s_band[w][lane] = (lane < width) ? a : 0.f;
    if (lane < width) g_attn_band[(b * Nn + i) * 32 + lane] = a;
    __syncwarp();

    float* rowp = out_attn + ((size_t)(b * Nn + i)) * Nn;
#pragma unroll
    for (int t = 0; t < 16; t++) {
        int j4 = (t * 32 + lane) * 4;
        float4 o = make_float4(0.f, 0.f, 0.f, 0.f);
        if (j4 + 3 >= j0 && j4 <= j1) {
#pragma unroll
            for (int q = 0; q < 4; q++) {
                int j = j4 + q;
                if (j >= j0 && j <= j1) ((float*)&o)[q] = s_band[w][j - j0];
            }
        }
        *(float4*)&rowp[j4] = o;
    }
}

// ---------------- K5: banded attn @ mem, fp16 HMMA, diag windows, fc=128 ----
// block = 64 i-rows x 128 f; smem 40704B -> 4-5 CTAs/SM.
#define MW_A0 0
#define MW_A1 7168
#define MW_M  14336
#define MW_SMEM (14336 + 26112 + 256)

__global__ void __launch_bounds__(256, 4)
k_memw(const float* __restrict__ sig, const float* __restrict__ mem,
       float* __restrict__ out_mem) {
    extern __shared__ char smw[];
    uint32_t mwb = smem_u32(smw);
    int i0 = blockIdx.x * 64;
    int fc = blockIdx.y * 128;
    int b = blockIdx.z;
    int tid = threadIdx.x;
    int jv = i0 - HALF_WIN;       // virtual (signed) base; may be -15

    __half* s_a0 = (__half*)(smw + MW_A0);   // [64][56]
    __half* s_a1 = (__half*)(smw + MW_A1);
    __half* s_m  = (__half*)(smw + MW_M);    // [96][136]

#pragma unroll
    for (int q = 0; q < 14; q++) {
        int p = q * 256 + tid;
        if (p < 3584) ((uint32_t*)smw)[p] = 0u;
    }
    __syncthreads();

    // fill attn band (fp16 split) into per-group windows relative to jv
#pragma unroll
    for (int q8 = 0; q8 < 8; q8++) {
        int q = q8 * 256 + tid;
        int r = q >> 5, l = q & 31;
        int i = i0 + r;
        int j0 = max(0, i - HALF_WIN);
        int j1 = min(Nn - 1, i + HALF_WIN);
        if (l <= j1 - j0) {
            float a = g_attn_band[(b * Nn + i) * 32 + l];
            __half a0 = __float2half_rn(a);
            float res = a - __half2float(a0);
            int col = (j0 + l) - jv - (r & ~15);   // in [r&15, 45]
            s_a0[r * 56 + col] = a0;
            s_a1[r * 56 + col] = __float2half_rn(res);
        }
    }
    // fill mem tile [96][136]: 96 rows x 32 float4 = 3072 -> 12 per thread
    {
        float4 v[12];
#pragma unroll
        for (int q = 0; q < 12; q++) {
            int p = q * 256 + tid;
            int row = p >> 5;
            int f4 = (p & 31) * 4;
            int ja = jv + row;
            if (ja >= 0 && ja < Nn)
                v[q] = *(const float4*)&mem[(size_t)(b * Nn + ja) * Kk + fc + f4];
            else
                v[q] = make_float4(0.f, 0.f, 0.f, 0.f);
        }
#pragma unroll
        for (int q = 0; q < 12; q++) {
            int p = q * 256 + tid;
            int row = p >> 5;
            int f4 = (p & 31) * 4;
            *(__half2*)&s_m[row * 136 + f4] = __floats2half2_rn(v[q].x, v[q].y);
            *(__half2*)&s_m[row * 136 + f4 + 2] = __floats2half2_rn(v[q].z, v[q].w);
        }
    }
    __syncthreads();

    int wid = tid >> 5, lane = tid & 31;
    uint32_t a0b = mwb + MW_A0;
    uint32_t a1b = mwb + MW_A1;
    uint32_t mb = mwb + MW_M;

    float acc[4][2][4];   // [mi][t][4]
#pragma unroll
    for (int mi = 0; mi < 4; mi++)
#pragma unroll
        for (int t = 0; t < 2; t++)
#pragma unroll
            for (int c = 0; c < 4; c++) acc[mi][t][c] = 0.f;

    // loop over absolute k-steps; share B fragment across the <=3 groups using it
#pragma unroll
    for (int q = 0; q < 6; q++) {
        uint32_t fb[2][2];
        uint32_t krow = q * 16 + (lane & 15);
#pragma unroll
        for (int t = 0; t < 2; t++) {
            uint32_t ncol = (wid * 2 + t) * 8;
            ldsm2t(mb + (krow * 136 + ncol) * 2, fb[t]);
        }
        int mlo = (q - 2 > 0) ? q - 2 : 0;
        int mhi = (q < 3) ? q : 3;
#pragma unroll
        for (int mi = 0; mi < 4; mi++) {
            if (mi < mlo || mi > mhi) continue;
            int ks = q - mi;    // 0..2
            uint32_t row = mi * 16 + (lane & 15);
            uint32_t col = ks * 16 + ((lane >> 4) << 3);
            uint32_t fa0[4], fa1[4];
            ldsm4(a0b + (row * 56 + col) * 2, fa0);
            ldsm4(a1b + (row * 56 + col) * 2, fa1);
#pragma unroll
            for (int t = 0; t < 2; t++) {
                mma16816h(acc[mi][t], fa0, fb[t]);
                mma16816h(acc[mi][t], fa1, fb[t]);
            }
        }
    }

    // blend + store directly from fragments
    int g = lane >> 2, t4 = lane & 3;
#pragma unroll
    for (int mi = 0; mi < 4; mi++) {
#pragma unroll
        for (int t = 0; t < 2; t++) {
            int col = wid * 16 + t * 8 + 2 * t4;
            int row0 = i0 + mi * 16 + g;
            size_t base0 = (size_t)(b * Nn + row0) * Kk + fc + col;
            size_t base1 = (size_t)(b * Nn + row0 + 8) * Kk + fc + col;
            float2 sg0 = *(const float2*)&sig[base0];
            float2 sg1 = *(const float2*)&sig[base1];
            float2 o0 = make_float2(0.5f * sg0.x + 0.5f * acc[mi][t][0],
                                    0.5f * sg0.y + 0.5f * acc[mi][t][1]);
            float2 o1 = make_float2(0.5f * sg1.x + 0.5f * acc[mi][t][2],
                                    0.5f * sg1.y + 0.5f * acc[mi][t][3]);
            *(float2*)&out_mem[base0] = o0;
            *(float2*)&out_mem[base1] = o1;
        }
    }
}

// ---------------- launch ----------------
extern "C" void kernel_launch(void* const* d_in, const int* in_sizes, int n_in,
                              void* d_out, int out_size) {
    const float* sig   = (const float*)d_in[0];
    const float* mem   = (const float*)d_in[1];
    const float* w     = (const float*)d_in[2];
    const float* bias  = (const float*)d_in[3];
    const float* gamma = (const float*)d_in[4];
    const float* beta  = (const float*)d_in[5];
    float* out_mem  = (float*)d_out;
    float* out_attn = (float*)d_out + (size_t)Bsz * Nn * Kk;

    static bool attr_done = false;
    if (!attr_done) {
        cudaFuncSetAttribute(k_gemm, cudaFuncAttributeMaxDynamicSharedMemorySize, GEMM_SMEM);
        cudaFuncSetAttribute(k_memw, cudaFuncAttributeMaxDynamicSharedMemorySize, MW_SMEM);
        attr_done = true;
    }

    k_wsplit<<<192, 256>>>(w);                               // launch 0
    k_gemm<<<Mm / 128, 256, GEMM_SMEM>>>(sig, mem, bias);    // launch 1
    k_attn<<<dim3(Nn / 8, Bsz), 256>>>(gamma, beta, out_attn); // launch 2
    k_memw<<<dim3(Nn / 64, 24, Bsz), 256, MW_SMEM>>>(sig, mem, out_mem); // launch 3 -> ncu
}